// round 4
// baseline (speedup 1.0000x reference)
#include <cuda_runtime.h>

#define Nn 10000
#define Ee 100000
#define Cc 32
#define Gg 64
#define BN_EPS 1e-5f

// ---- scratch (static device globals; no runtime allocation) ----
__device__ float g_T[(size_t)Nn * Cc * Cc];   // 40.96 MB per-node transformed weights
__device__ float g_xb[Nn * Cc];               // b2 contribution per node
__device__ float g_agg[Nn * Cc];              // scatter-sum accumulator
__device__ float g_h1[Nn * Cc];               // layer-1 output
__device__ float g_h2[Nn * Cc];               // layer-2 output
__device__ float g_deg[Nn];                   // in-degree (by dst)
__device__ float g_pool[Gg * Cc];
__device__ float g_pcnt[Gg];
// CSR-by-src (built once, reused by both layers)
__device__ int   g_scnt[Nn];                  // out-degree (by src)
__device__ int   g_cur[Nn];                   // scatter cursor
__device__ int   g_rowptr[Nn + 1];
__device__ int   g_eids[Ee];                  // edge ids grouped by src

// ---- zero kernels ----
__global__ void k_zero_all() {
    int i = blockIdx.x * blockDim.x + threadIdx.x;
    if (i < Nn * Cc) g_agg[i] = 0.f;
    if (i < Nn) { g_deg[i] = 0.f; g_scnt[i] = 0; g_cur[i] = 0; }
    if (i < Gg * Cc) g_pool[i] = 0.f;
    if (i < Gg)      g_pcnt[i] = 0.f;
}
__global__ void k_zero_agg() {
    int i = blockIdx.x * blockDim.x + threadIdx.x;
    if (i < Nn * Cc) g_agg[i] = 0.f;
}

// ---- degree by dst (float) + out-degree histogram by src (int) ----
__global__ void k_prep(const int* __restrict__ ei) {
    int e = blockIdx.x * blockDim.x + threadIdx.x;
    if (e < Ee) {
        atomicAdd(&g_deg[ei[Ee + e]], 1.f);
        atomicAdd(&g_scnt[ei[e]], 1);
    }
}

// ---- single-block exclusive scan, warp-shfl based (3 barrier rounds total) ----
__global__ void __launch_bounds__(1024, 1) k_scan() {
    const int ITEMS = 10;                     // 1024*10 >= Nn
    int t = threadIdx.x;
    int base = t * ITEMS;
    int v[ITEMS];
    int sum = 0;
#pragma unroll
    for (int i = 0; i < ITEMS; i++) {
        int idx = base + i;
        int c = (idx < Nn) ? g_scnt[idx] : 0;
        v[i] = sum;                           // thread-local exclusive prefix
        sum += c;
    }
    int lane = t & 31, wid = t >> 5;
    // warp inclusive scan of thread sums
    int s = sum;
#pragma unroll
    for (int d = 1; d < 32; d <<= 1) {
        int u = __shfl_up_sync(0xffffffffu, s, d);
        if (lane >= d) s += u;
    }
    __shared__ int wsum[32];
    if (lane == 31) wsum[wid] = s;
    __syncthreads();
    if (wid == 0) {
        int ws = wsum[lane];
#pragma unroll
        for (int d = 1; d < 32; d <<= 1) {
            int u = __shfl_up_sync(0xffffffffu, ws, d);
            if (lane >= d) ws += u;
        }
        wsum[lane] = ws;
    }
    __syncthreads();
    int warp_off = (wid > 0) ? wsum[wid - 1] : 0;
    int thread_off = warp_off + (s - sum);    // exclusive prefix for this thread
#pragma unroll
    for (int i = 0; i < ITEMS; i++) {
        int idx = base + i;
        if (idx < Nn) g_rowptr[idx] = thread_off + v[i];
    }
    if (t == 1023) g_rowptr[Nn] = thread_off + sum;   // == Ee
}

// ---- scatter edge ids into CSR buckets ----
__global__ void k_fill(const int* __restrict__ ei) {
    int e = blockIdx.x * blockDim.x + threadIdx.x;
    if (e < Ee) {
        int s = ei[e];
        int pos = g_rowptr[s] + atomicAdd(&g_cur[s], 1);
        g_eids[pos] = e;
    }
}

// ---- xb[n,o] = sum_i x[n,i] * b2[i*C+o] ----
__global__ void k_xb(const float* __restrict__ x, const float* __restrict__ b2) {
    int t = blockIdx.x * blockDim.x + threadIdx.x;
    if (t >= Nn * Cc) return;
    int n = t >> 5, o = t & 31;
    const float* xr = x + n * Cc;
    float acc = 0.f;
#pragma unroll
    for (int i = 0; i < Cc; i++) acc += xr[i] * b2[i * Cc + o];
    g_xb[t] = acc;
}

// ---- T[n,k,o] = sum_i x[n,i] * w2[k, i*C+o] ----
__global__ void __launch_bounds__(1024, 1)
k_T(const float* __restrict__ x, const float* __restrict__ w2) {
    int k = threadIdx.x >> 5, o = threadIdx.x & 31;
    float w[32];
#pragma unroll
    for (int i = 0; i < 32; i++) w[i] = w2[k * 1024 + i * 32 + o];

    __shared__ float xs[32][32];
    int npb = (Nn + gridDim.x - 1) / gridDim.x;
    int n0 = blockIdx.x * npb;
    int n1 = min(n0 + npb, Nn);
    for (int nb = n0; nb < n1; nb += 32) {
        int cnt = min(32, n1 - nb);
        if ((int)threadIdx.x < cnt * 32)
            ((float*)xs)[threadIdx.x] = x[nb * 32 + threadIdx.x];
        __syncthreads();
        for (int j = 0; j < cnt; j++) {
            const float4* xr = (const float4*)xs[j];
            float acc = 0.f;
#pragma unroll
            for (int i4 = 0; i4 < 8; i4++) {
                float4 xv = xr[i4];
                acc += xv.x * w[4 * i4 + 0];
                acc += xv.y * w[4 * i4 + 1];
                acc += xv.z * w[4 * i4 + 2];
                acc += xv.w * w[4 * i4 + 3];
            }
            g_T[(size_t)(nb + j) * 1024 + threadIdx.x] = acc;
        }
        __syncthreads();
    }
}

// ---- edge kernel: one warp per CSR position (edges grouped by src -> L1 reuse of T row) ----
__global__ void k_edge2(const float* __restrict__ ea, const int* __restrict__ ei,
                        const float* __restrict__ w1, const float* __restrict__ b1) {
    int idx = (blockIdx.x * blockDim.x + threadIdx.x) >> 5;
    if (idx >= Ee) return;
    int o = threadIdx.x & 31;
    int e = g_eids[idx];
    int src = __ldg(&ei[e]);
    int dst = __ldg(&ei[Ee + e]);
    float4 a = __ldg((const float4*)ea + e);
    float h = fmaxf(b1[o] + a.x * w1[o] + a.y * w1[32 + o]
                          + a.z * w1[64 + o] + a.w * w1[96 + o], 0.f);

    const float* Tp = g_T + (size_t)src * 1024 + o;   // same row for sibling warps -> L1 hits
    float acc = g_xb[src * 32 + o];
#pragma unroll
    for (int k = 0; k < 32; k++)
        acc += __shfl_sync(0xffffffffu, h, k) * Tp[k * 32];

    atomicAdd(&g_agg[dst * 32 + o], acc);
}

// ---- node update: mean-agg + root matmul + bias + BN + ReLU ----
__global__ void k_node(const float* __restrict__ xin, const float* __restrict__ root,
                       const float* __restrict__ bias,
                       const float* __restrict__ bg, const float* __restrict__ bb,
                       const float* __restrict__ bm, const float* __restrict__ bv,
                       float* __restrict__ out) {
    int t = blockIdx.x * blockDim.x + threadIdx.x;
    if (t >= Nn * Cc) return;
    int n = t >> 5, o = t & 31;
    float val = g_agg[t] / fmaxf(g_deg[n], 1.f);
    const float* xr = xin + n * Cc;
#pragma unroll
    for (int i = 0; i < Cc; i++) val += xr[i] * root[i * Cc + o];
    val += bias[o];
    val = (val - bm[o]) * rsqrtf(bv[o] + BN_EPS) * bg[o] + bb[o];
    out[t] = fmaxf(val, 0.f);
}

// ---- global mean pool ----
__global__ void k_pool(const int* __restrict__ batch) {
    int t = blockIdx.x * blockDim.x + threadIdx.x;
    if (t >= Nn * Cc) return;
    int n = t >> 5, o = t & 31;
    int gph = batch[n];
    atomicAdd(&g_pool[gph * Cc + o], g_h2[t]);
    if (o == 0) atomicAdd(&g_pcnt[gph], 1.f);
}

// ---- readout MLP ----
__global__ void k_readout(const float* __restrict__ r1w, const float* __restrict__ r1b,
                          const float* __restrict__ r2w, const float* __restrict__ r2b,
                          float* __restrict__ out) {
    int gph = blockIdx.x * blockDim.x + threadIdx.x;
    if (gph >= Gg) return;
    float c = fmaxf(g_pcnt[gph], 1.f);
    float p[Cc];
#pragma unroll
    for (int o = 0; o < Cc; o++) p[o] = g_pool[gph * Cc + o] / c;
    float res = r2b[0];
#pragma unroll
    for (int j = 0; j < 16; j++) {
        float hid = r1b[j];
#pragma unroll
        for (int o = 0; o < Cc; o++) hid += p[o] * r1w[o * 16 + j];
        res += fmaxf(hid, 0.f) * r2w[j];
    }
    out[gph] = res;
}

extern "C" void kernel_launch(void* const* d_in, const int* in_sizes, int n_in,
                              void* d_out, int out_size) {
    const float* x     = (const float*)d_in[0];
    const float* ea    = (const float*)d_in[1];
    const float* e1w1  = (const float*)d_in[2];
    const float* e1b1  = (const float*)d_in[3];
    const float* e1w2  = (const float*)d_in[4];
    const float* e1b2  = (const float*)d_in[5];
    const float* root1 = (const float*)d_in[6];
    const float* bias1 = (const float*)d_in[7];
    const float* e2w1  = (const float*)d_in[8];
    const float* e2b1  = (const float*)d_in[9];
    const float* e2w2  = (const float*)d_in[10];
    const float* e2b2  = (const float*)d_in[11];
    const float* root2 = (const float*)d_in[12];
    const float* bias2 = (const float*)d_in[13];
    const float* bn1g  = (const float*)d_in[14];
    const float* bn1b  = (const float*)d_in[15];
    const float* bn1m  = (const float*)d_in[16];
    const float* bn1v  = (const float*)d_in[17];
    const float* bn2g  = (const float*)d_in[18];
    const float* bn2b  = (const float*)d_in[19];
    const float* bn2m  = (const float*)d_in[20];
    const float* bn2v  = (const float*)d_in[21];
    const float* r1w   = (const float*)d_in[22];
    const float* r1b   = (const float*)d_in[23];
    const float* r2w   = (const float*)d_in[24];
    const float* r2b   = (const float*)d_in[25];
    const int*   eidx  = (const int*)d_in[26];
    const int*   batch = (const int*)d_in[27];
    float* out = (float*)d_out;

    float *p_h1 = nullptr, *p_h2 = nullptr;
    cudaGetSymbolAddress((void**)&p_h1, g_h1);
    cudaGetSymbolAddress((void**)&p_h2, g_h2);

    const int THR = 256;
    const int gNC = (Nn * Cc + THR - 1) / THR;        // 1250 blocks
    const int gE  = (Ee + THR - 1) / THR;
    const int gEW = (Ee * 32) / THR;                  // warp per edge position

    // CSR build (shared by both layers)
    k_zero_all<<<gNC, THR>>>();
    k_prep<<<gE, THR>>>(eidx);
    k_scan<<<1, 1024>>>();
    k_fill<<<gE, THR>>>(eidx);

    // layer 1
    k_xb<<<gNC, THR>>>(x, e1b2);
    k_T<<<148, 1024>>>(x, e1w2);
    k_edge2<<<gEW, THR>>>(ea, eidx, e1w1, e1b1);
    k_node<<<gNC, THR>>>(x, root1, bias1, bn1g, bn1b, bn1m, bn1v, p_h1);

    // layer 2
    k_zero_agg<<<gNC, THR>>>();
    k_xb<<<gNC, THR>>>(p_h1, e2b2);
    k_T<<<148, 1024>>>(p_h1, e2w2);
    k_edge2<<<gEW, THR>>>(ea, eidx, e2w1, e2b1);
    k_node<<<gNC, THR>>>(p_h1, root2, bias2, bn2g, bn2b, bn2m, bn2v, p_h2);

    // pool + readout
    k_pool<<<gNC, THR>>>(batch);
    k_readout<<<1, 64>>>(r1w, r1b, r2w, r2b, out);
}

// round 5
// speedup vs baseline: 1.1527x; 1.1527x over previous
#include <cuda_runtime.h>

#define Nn 10000
#define Ee 100000
#define Cc 32
#define Gg 64
#define BN_EPS 1e-5f

typedef unsigned long long u64;

// ---- scratch (static device globals; zero-initialized at load) ----
__device__ float g_T[(size_t)Nn * Cc * Cc];   // 40.96 MB per-node transformed weights
__device__ float g_xb[Nn * Cc];               // b2 contribution per node
__device__ float g_agg[Nn * Cc];              // scatter-sum accumulator (reset in k_node)
__device__ float g_h1[Nn * Cc];               // layer-1 output
__device__ float g_deg[Nn];                   // in-degree by dst (reset in node2)
__device__ float g_pool[Gg * Cc];             // (reset in readout)
__device__ float g_pcnt[Gg];                  // (reset in readout)

// packed f32x2 fma (sm_100+ only; ptxas will not auto-fuse)
__device__ __forceinline__ void fma2(u64& d, u64 a, u64 b) {
    asm("fma.rn.f32x2 %0, %1, %2, %0;" : "+l"(d) : "l"(a), "l"(b));
}
__device__ __forceinline__ float2 unpack2(u64 v) {
    float2 r;
    asm("mov.b64 {%0, %1}, %2;" : "=f"(r.x), "=f"(r.y) : "l"(v));
    return r;
}

// ---- in-degree by dst ----
__global__ void k_deg(const int* __restrict__ ei) {
    int e = blockIdx.x * blockDim.x + threadIdx.x;
    if (e < Ee) atomicAdd(&g_deg[ei[Ee + e]], 1.f);
}

// ---- xb[n,o] = sum_i x[n,i] * b2[i*C+o] ----
__global__ void k_xb(const float* __restrict__ x, const float* __restrict__ b2) {
    int t = blockIdx.x * blockDim.x + threadIdx.x;
    if (t >= Nn * Cc) return;
    int n = t >> 5, o = t & 31;
    const float* xr = x + n * Cc;
    float a0 = 0.f, a1 = 0.f;
#pragma unroll
    for (int i = 0; i < Cc; i += 2) {
        a0 += __ldg(&xr[i])     * b2[i * Cc + o];
        a1 += __ldg(&xr[i + 1]) * b2[(i + 1) * Cc + o];
    }
    g_xb[t] = a0 + a1;
}

// ---- T[n,k,o] = sum_i x[n,i] * w2[k, i*C+o], packed f32x2 ----
// 512 threads: k = tid>>4 (0..31), p = tid&15 -> outputs o = 2p, 2p+1.
__global__ void __launch_bounds__(512, 1)
k_T(const float* __restrict__ x, const float* __restrict__ w2) {
    int k = threadIdx.x >> 4, p = threadIdx.x & 15;

    // per-thread packed weight column: w[i] = (w2[k,i*32+2p], w2[k,i*32+2p+1])
    u64 w[32];
    const u64* w2p = (const u64*)w2;   // device allocs are 256B aligned
#pragma unroll
    for (int i = 0; i < 32; i++) w[i] = w2p[k * 512 + i * 16 + p];

    __shared__ u64 xs2[32][32];        // pre-splatted x tile: xs2[j][i] = (x,x)

    int npb = (Nn + gridDim.x - 1) / gridDim.x;
    int n0 = blockIdx.x * npb;
    int n1 = min(n0 + npb, Nn);
    for (int nb = n0; nb < n1; nb += 32) {
        int cnt = min(32, n1 - nb);
        // fill splat tile (512 threads, 1024 entries)
#pragma unroll
        for (int r = 0; r < 2; r++) {
            int idx = threadIdx.x + r * 512;
            int jl = idx >> 5, il = idx & 31;
            float v = (nb + jl < n1) ? x[(nb + jl) * 32 + il] : 0.f;
            float2 sp; sp.x = v; sp.y = v;
            xs2[jl][il] = *(const u64*)&sp;
        }
        __syncthreads();
        for (int j = 0; j < cnt; j++) {
            const ulonglong2* row = (const ulonglong2*)xs2[j];
            u64 a0 = 0ull, a1 = 0ull;
#pragma unroll
            for (int i4 = 0; i4 < 16; i4++) {
                ulonglong2 q = row[i4];        // two splats: x[2i4], x[2i4+1]
                fma2(a0, w[2 * i4],     q.x);
                fma2(a1, w[2 * i4 + 1], q.y);
            }
            float2 fa = unpack2(a0), fb = unpack2(a1);
            float2 res; res.x = fa.x + fb.x; res.y = fa.y + fb.y;
            *(float2*)(g_T + (size_t)(nb + j) * 1024 + k * 32 + 2 * p) = res;
        }
        __syncthreads();
    }
}

// ---- edge kernel: two edges per warp, lane = output channel o ----
__global__ void k_edge(const float* __restrict__ ea, const int* __restrict__ ei,
                       const float* __restrict__ w1, const float* __restrict__ b1) {
    int wrp = (blockIdx.x * blockDim.x + threadIdx.x) >> 5;
    if (wrp >= Ee / 2) return;
    int o = threadIdx.x & 31;
    int e0 = 2 * wrp, e1 = 2 * wrp + 1;
    int s0 = __ldg(&ei[e0]),      s1 = __ldg(&ei[e1]);
    int d0 = __ldg(&ei[Ee + e0]), d1 = __ldg(&ei[Ee + e1]);
    float4 a0 = __ldg((const float4*)ea + e0);
    float4 a1 = __ldg((const float4*)ea + e1);
    float w10 = w1[o], w11 = w1[32 + o], w12 = w1[64 + o], w13 = w1[96 + o];
    float bb = b1[o];
    float h0 = fmaxf(bb + a0.x * w10 + a0.y * w11 + a0.z * w12 + a0.w * w13, 0.f);
    float h1 = fmaxf(bb + a1.x * w10 + a1.y * w11 + a1.z * w12 + a1.w * w13, 0.f);

    const float* T0 = g_T + (size_t)s0 * 1024 + o;
    const float* T1 = g_T + (size_t)s1 * 1024 + o;
    float p0 = 0.f, q0 = 0.f, p1 = 0.f, q1 = 0.f;   // 4 independent chains
#pragma unroll
    for (int k = 0; k < 32; k += 2) {
        p0 += __shfl_sync(0xffffffffu, h0, k)     * T0[k * 32];
        q0 += __shfl_sync(0xffffffffu, h0, k + 1) * T0[(k + 1) * 32];
        p1 += __shfl_sync(0xffffffffu, h1, k)     * T1[k * 32];
        q1 += __shfl_sync(0xffffffffu, h1, k + 1) * T1[(k + 1) * 32];
    }
    atomicAdd(&g_agg[d0 * 32 + o], g_xb[s0 * 32 + o] + p0 + q0);
    atomicAdd(&g_agg[d1 * 32 + o], g_xb[s1 * 32 + o] + p1 + q1);
}

// ---- node update layer 1: mean-agg + root + bias + BN + ReLU; resets agg ----
__global__ void k_node1(const float* __restrict__ xin, const float* __restrict__ root,
                        const float* __restrict__ bias,
                        const float* __restrict__ bg, const float* __restrict__ bb,
                        const float* __restrict__ bm, const float* __restrict__ bv,
                        float* __restrict__ out) {
    int t = blockIdx.x * blockDim.x + threadIdx.x;
    if (t >= Nn * Cc) return;
    int n = t >> 5, o = t & 31;
    float val = g_agg[t] / fmaxf(g_deg[n], 1.f);
    g_agg[t] = 0.f;                                  // reset for layer 2
    const float* xr = xin + n * Cc;
    float a0 = 0.f, a1 = 0.f;
#pragma unroll
    for (int i = 0; i < Cc; i += 2) {
        a0 += __ldg(&xr[i])     * root[i * Cc + o];
        a1 += __ldg(&xr[i + 1]) * root[(i + 1) * Cc + o];
    }
    val += a0 + a1 + bias[o];
    val = (val - bm[o]) * rsqrtf(bv[o] + BN_EPS) * bg[o] + bb[o];
    out[t] = fmaxf(val, 0.f);
}

// ---- node update layer 2 + fused mean-pool scatter; resets agg & deg ----
__global__ void k_node2(const float* __restrict__ xin, const float* __restrict__ root,
                        const float* __restrict__ bias,
                        const float* __restrict__ bg, const float* __restrict__ bb,
                        const float* __restrict__ bm, const float* __restrict__ bv,
                        const int* __restrict__ batch) {
    int t = blockIdx.x * blockDim.x + threadIdx.x;
    if (t >= Nn * Cc) return;
    int n = t >> 5, o = t & 31;
    float dg = g_deg[n];
    float val = g_agg[t] / fmaxf(dg, 1.f);
    g_agg[t] = 0.f;                                  // reset for next replay
    __syncwarp();
    if (o == 0) g_deg[n] = 0.f;                      // all readers of deg[n] are this warp
    const float* xr = xin + n * Cc;
    float a0 = 0.f, a1 = 0.f;
#pragma unroll
    for (int i = 0; i < Cc; i += 2) {
        a0 += __ldg(&xr[i])     * root[i * Cc + o];
        a1 += __ldg(&xr[i + 1]) * root[(i + 1) * Cc + o];
    }
    val += a0 + a1 + bias[o];
    val = (val - bm[o]) * rsqrtf(bv[o] + BN_EPS) * bg[o] + bb[o];
    val = fmaxf(val, 0.f);
    int gph = __ldg(&batch[n]);
    atomicAdd(&g_pool[gph * Cc + o], val);
    if (o == 0) atomicAdd(&g_pcnt[gph], 1.f);
}

// ---- readout MLP; resets pool/pcnt ----
__global__ void k_readout(const float* __restrict__ r1w, const float* __restrict__ r1b,
                          const float* __restrict__ r2w, const float* __restrict__ r2b,
                          float* __restrict__ out) {
    int gph = blockIdx.x * blockDim.x + threadIdx.x;
    if (gph >= Gg) return;
    float c = fmaxf(g_pcnt[gph], 1.f);
    float p[Cc];
#pragma unroll
    for (int o = 0; o < Cc; o++) p[o] = g_pool[gph * Cc + o] / c;
    float res = r2b[0];
#pragma unroll
    for (int j = 0; j < 16; j++) {
        float hid = r1b[j];
#pragma unroll
        for (int o = 0; o < Cc; o++) hid += p[o] * r1w[o * 16 + j];
        res += fmaxf(hid, 0.f) * r2w[j];
    }
    out[gph] = res;
    // reset pooled state for next replay
#pragma unroll
    for (int o = 0; o < Cc; o++) g_pool[gph * Cc + o] = 0.f;
    g_pcnt[gph] = 0.f;
}

extern "C" void kernel_launch(void* const* d_in, const int* in_sizes, int n_in,
                              void* d_out, int out_size) {
    const float* x     = (const float*)d_in[0];
    const float* ea    = (const float*)d_in[1];
    const float* e1w1  = (const float*)d_in[2];
    const float* e1b1  = (const float*)d_in[3];
    const float* e1w2  = (const float*)d_in[4];
    const float* e1b2  = (const float*)d_in[5];
    const float* root1 = (const float*)d_in[6];
    const float* bias1 = (const float*)d_in[7];
    const float* e2w1  = (const float*)d_in[8];
    const float* e2b1  = (const float*)d_in[9];
    const float* e2w2  = (const float*)d_in[10];
    const float* e2b2  = (const float*)d_in[11];
    const float* root2 = (const float*)d_in[12];
    const float* bias2 = (const float*)d_in[13];
    const float* bn1g  = (const float*)d_in[14];
    const float* bn1b  = (const float*)d_in[15];
    const float* bn1m  = (const float*)d_in[16];
    const float* bn1v  = (const float*)d_in[17];
    const float* bn2g  = (const float*)d_in[18];
    const float* bn2b  = (const float*)d_in[19];
    const float* bn2m  = (const float*)d_in[20];
    const float* bn2v  = (const float*)d_in[21];
    const float* r1w   = (const float*)d_in[22];
    const float* r1b   = (const float*)d_in[23];
    const float* r2w   = (const float*)d_in[24];
    const float* r2b   = (const float*)d_in[25];
    const int*   eidx  = (const int*)d_in[26];
    const int*   batch = (const int*)d_in[27];
    float* out = (float*)d_out;

    float* p_h1 = nullptr;
    cudaGetSymbolAddress((void**)&p_h1, g_h1);

    const int THR = 256;
    const int gNC = (Nn * Cc + THR - 1) / THR;        // 1250 blocks
    const int gE  = (Ee + THR - 1) / THR;
    const int gEW = (Ee / 2 * 32 + THR - 1) / THR;    // 2 edges per warp: 6250 blocks

    k_deg<<<gE, THR>>>(eidx);

    // layer 1
    k_xb<<<gNC, THR>>>(x, e1b2);
    k_T<<<148, 512>>>(x, e1w2);
    k_edge<<<gEW, THR>>>(ea, eidx, e1w1, e1b1);
    k_node1<<<gNC, THR>>>(x, root1, bias1, bn1g, bn1b, bn1m, bn1v, p_h1);

    // layer 2
    k_xb<<<gNC, THR>>>(p_h1, e2b2);
    k_T<<<148, 512>>>(p_h1, e2w2);
    k_edge<<<gEW, THR>>>(ea, eidx, e2w1, e2b1);
    k_node2<<<gNC, THR>>>(p_h1, root2, bias2, bn2g, bn2b, bn2m, bn2v, batch);

    // readout (pool already scattered by k_node2)
    k_readout<<<1, 64>>>(r1w, r1b, r2w, r2b, out);
}

// round 6
// speedup vs baseline: 1.2455x; 1.0805x over previous
#include <cuda_runtime.h>
#include <cuda_fp16.h>

#define Nn 10000
#define Ee 100000
#define Cc 32
#define Gg 64
#define BN_EPS 1e-5f

typedef unsigned long long u64;

// ---- scratch (static device globals; zero-initialized at load) ----
__device__ __half2 g_Th[(size_t)Nn * 512];    // 10.24 MB: T[n][kpair][o] as half2 (k even/odd)
__device__ float g_xb[Nn * Cc];               // b2 contribution per node
__device__ float g_agg[Nn * Cc];              // scatter-sum accumulator (reset in k_node)
__device__ float g_h1[Nn * Cc];               // layer-1 output
__device__ float g_deg[Nn];                   // in-degree by dst (reset in node2)
__device__ float g_pool[Gg * Cc];             // (reset in readout)
__device__ float g_pcnt[Gg];                  // (reset in readout)

// packed f32x2 helpers (sm_100+; ptxas will not auto-fuse)
__device__ __forceinline__ void fma2(u64& d, u64 a, u64 b) {
    asm("fma.rn.f32x2 %0, %1, %2, %0;" : "+l"(d) : "l"(a), "l"(b));
}
__device__ __forceinline__ u64 pack2(float lo, float hi) {
    u64 r;
    asm("mov.b64 %0, {%1, %2};" : "=l"(r) : "f"(lo), "f"(hi));
    return r;
}
__device__ __forceinline__ float2 unpack2(u64 v) {
    float2 r;
    asm("mov.b64 {%0, %1}, %2;" : "=f"(r.x), "=f"(r.y) : "l"(v));
    return r;
}

// ---- in-degree by dst ----
__global__ void k_deg(const int* __restrict__ ei) {
    int e = blockIdx.x * blockDim.x + threadIdx.x;
    if (e < Ee) atomicAdd(&g_deg[ei[Ee + e]], 1.f);
}

// ---- xb[n,o] = sum_i x[n,i] * b2[i*C+o] ----
__global__ void k_xb(const float* __restrict__ x, const float* __restrict__ b2) {
    int t = blockIdx.x * blockDim.x + threadIdx.x;
    if (t >= Nn * Cc) return;
    int n = t >> 5, o = t & 31;
    const float* xr = x + n * Cc;
    float a0 = 0.f, a1 = 0.f;
#pragma unroll
    for (int i = 0; i < Cc; i += 2) {
        a0 += __ldg(&xr[i])     * b2[i * Cc + o];
        a1 += __ldg(&xr[i + 1]) * b2[(i + 1) * Cc + o];
    }
    g_xb[t] = a0 + a1;
}

// ---- T[n,k,o] = sum_i x[n,i] * w2[k, i*C+o], fp16 output, k-paired layout ----
// 512 threads: kp = tid>>5 (0..15) -> k pair (2kp, 2kp+1); o = tid&31.
// Thread accumulates both k's simultaneously via packed f32x2, stores one half2.
__global__ void __launch_bounds__(512, 1)
k_T(const float* __restrict__ x, const float* __restrict__ w2) {
    int kp = threadIdx.x >> 5, o = threadIdx.x & 31;

    // w[i] = (w2[2kp, i*32+o], w2[2kp+1, i*32+o]) packed
    u64 w[32];
    const float* wa = w2 + (2 * kp) * 1024 + o;
    const float* wb = w2 + (2 * kp + 1) * 1024 + o;
#pragma unroll
    for (int i = 0; i < 32; i++) w[i] = pack2(__ldg(&wa[i * 32]), __ldg(&wb[i * 32]));

    __shared__ u64 xs2[32][32];        // splat tile: xs2[j][i] = (x[nb+j,i], x[nb+j,i])

    int npb = (Nn + gridDim.x - 1) / gridDim.x;
    int n0 = blockIdx.x * npb;
    int n1 = min(n0 + npb, Nn);
    for (int nb = n0; nb < n1; nb += 32) {
        int cnt = min(32, n1 - nb);
#pragma unroll
        for (int r = 0; r < 2; r++) {
            int idx = threadIdx.x + r * 512;
            int jl = idx >> 5, il = idx & 31;
            float v = (nb + jl < n1) ? x[(nb + jl) * 32 + il] : 0.f;
            xs2[jl][il] = pack2(v, v);
        }
        __syncthreads();
        for (int j = 0; j < cnt; j++) {
            const u64* row = xs2[j];
            u64 a0 = 0ull, a1 = 0ull;
#pragma unroll
            for (int i = 0; i < 32; i += 2) {
                fma2(a0, w[i],     row[i]);
                fma2(a1, w[i + 1], row[i + 1]);
            }
            float2 fa = unpack2(a0), fb = unpack2(a1);
            g_Th[(size_t)(nb + j) * 512 + kp * 32 + o] =
                __floats2half2_rn(fa.x + fb.x, fa.y + fb.y);
        }
        __syncthreads();
    }
}

// ---- edge kernel: two edges per warp, lane = output channel o; T in half2 ----
__global__ void k_edge(const float* __restrict__ ea, const int* __restrict__ ei,
                       const float* __restrict__ w1, const float* __restrict__ b1) {
    int wrp = (blockIdx.x * blockDim.x + threadIdx.x) >> 5;
    if (wrp >= Ee / 2) return;
    int o = threadIdx.x & 31;
    int e0 = 2 * wrp, e1 = 2 * wrp + 1;
    int s0 = __ldg(&ei[e0]),      s1 = __ldg(&ei[e1]);
    int d0 = __ldg(&ei[Ee + e0]), d1 = __ldg(&ei[Ee + e1]);
    float4 a0 = __ldg((const float4*)ea + e0);
    float4 a1 = __ldg((const float4*)ea + e1);
    float w10 = w1[o], w11 = w1[32 + o], w12 = w1[64 + o], w13 = w1[96 + o];
    float bb = b1[o];
    float h0 = fmaxf(bb + a0.x * w10 + a0.y * w11 + a0.z * w12 + a0.w * w13, 0.f);
    float h1 = fmaxf(bb + a1.x * w10 + a1.y * w11 + a1.z * w12 + a1.w * w13, 0.f);

    const __half2* T0 = g_Th + (size_t)s0 * 512 + o;
    const __half2* T1 = g_Th + (size_t)s1 * 512 + o;
    float p0 = 0.f, q0 = 0.f, p1 = 0.f, q1 = 0.f;   // 4 independent chains
#pragma unroll
    for (int kp = 0; kp < 16; kp++) {
        float2 t0 = __half22float2(T0[kp * 32]);
        float2 t1 = __half22float2(T1[kp * 32]);
        p0 += __shfl_sync(0xffffffffu, h0, 2 * kp)     * t0.x;
        q0 += __shfl_sync(0xffffffffu, h0, 2 * kp + 1) * t0.y;
        p1 += __shfl_sync(0xffffffffu, h1, 2 * kp)     * t1.x;
        q1 += __shfl_sync(0xffffffffu, h1, 2 * kp + 1) * t1.y;
    }
    atomicAdd(&g_agg[d0 * 32 + o], g_xb[s0 * 32 + o] + p0 + q0);
    atomicAdd(&g_agg[d1 * 32 + o], g_xb[s1 * 32 + o] + p1 + q1);
}

// ---- node update layer 1: mean-agg + root + bias + BN + ReLU; resets agg ----
__global__ void k_node1(const float* __restrict__ xin, const float* __restrict__ root,
                        const float* __restrict__ bias,
                        const float* __restrict__ bg, const float* __restrict__ bb,
                        const float* __restrict__ bm, const float* __restrict__ bv,
                        float* __restrict__ out) {
    int t = blockIdx.x * blockDim.x + threadIdx.x;
    if (t >= Nn * Cc) return;
    int n = t >> 5, o = t & 31;
    float val = g_agg[t] / fmaxf(g_deg[n], 1.f);
    g_agg[t] = 0.f;                                  // reset for layer 2
    const float* xr = xin + n * Cc;
    float a0 = 0.f, a1 = 0.f;
#pragma unroll
    for (int i = 0; i < Cc; i += 2) {
        a0 += __ldg(&xr[i])     * root[i * Cc + o];
        a1 += __ldg(&xr[i + 1]) * root[(i + 1) * Cc + o];
    }
    val += a0 + a1 + bias[o];
    val = (val - bm[o]) * rsqrtf(bv[o] + BN_EPS) * bg[o] + bb[o];
    out[t] = fmaxf(val, 0.f);
}

// ---- node update layer 2 + fused mean-pool scatter; resets agg & deg ----
__global__ void k_node2(const float* __restrict__ xin, const float* __restrict__ root,
                        const float* __restrict__ bias,
                        const float* __restrict__ bg, const float* __restrict__ bb,
                        const float* __restrict__ bm, const float* __restrict__ bv,
                        const int* __restrict__ batch) {
    int t = blockIdx.x * blockDim.x + threadIdx.x;
    if (t >= Nn * Cc) return;
    int n = t >> 5, o = t & 31;
    float dg = g_deg[n];
    float val = g_agg[t] / fmaxf(dg, 1.f);
    g_agg[t] = 0.f;                                  // reset for next replay
    __syncwarp();
    if (o == 0) g_deg[n] = 0.f;                      // all readers of deg[n] are this warp
    const float* xr = xin + n * Cc;
    float a0 = 0.f, a1 = 0.f;
#pragma unroll
    for (int i = 0; i < Cc; i += 2) {
        a0 += __ldg(&xr[i])     * root[i * Cc + o];
        a1 += __ldg(&xr[i + 1]) * root[(i + 1) * Cc + o];
    }
    val += a0 + a1 + bias[o];
    val = (val - bm[o]) * rsqrtf(bv[o] + BN_EPS) * bg[o] + bb[o];
    val = fmaxf(val, 0.f);
    int gph = __ldg(&batch[n]);
    atomicAdd(&g_pool[gph * Cc + o], val);
    if (o == 0) atomicAdd(&g_pcnt[gph], 1.f);
}

// ---- readout MLP; resets pool/pcnt ----
__global__ void k_readout(const float* __restrict__ r1w, const float* __restrict__ r1b,
                          const float* __restrict__ r2w, const float* __restrict__ r2b,
                          float* __restrict__ out) {
    int gph = blockIdx.x * blockDim.x + threadIdx.x;
    if (gph >= Gg) return;
    float c = fmaxf(g_pcnt[gph], 1.f);
    float p[Cc];
#pragma unroll
    for (int o = 0; o < Cc; o++) p[o] = g_pool[gph * Cc + o] / c;
    float res = r2b[0];
#pragma unroll
    for (int j = 0; j < 16; j++) {
        float hid = r1b[j];
#pragma unroll
        for (int o = 0; o < Cc; o++) hid += p[o] * r1w[o * 16 + j];
        res += fmaxf(hid, 0.f) * r2w[j];
    }
    out[gph] = res;
    // reset pooled state for next replay
#pragma unroll
    for (int o = 0; o < Cc; o++) g_pool[gph * Cc + o] = 0.f;
    g_pcnt[gph] = 0.f;
}

extern "C" void kernel_launch(void* const* d_in, const int* in_sizes, int n_in,
                              void* d_out, int out_size) {
    const float* x     = (const float*)d_in[0];
    const float* ea    = (const float*)d_in[1];
    const float* e1w1  = (const float*)d_in[2];
    const float* e1b1  = (const float*)d_in[3];
    const float* e1w2  = (const float*)d_in[4];
    const float* e1b2  = (const float*)d_in[5];
    const float* root1 = (const float*)d_in[6];
    const float* bias1 = (const float*)d_in[7];
    const float* e2w1  = (const float*)d_in[8];
    const float* e2b1  = (const float*)d_in[9];
    const float* e2w2  = (const float*)d_in[10];
    const float* e2b2  = (const float*)d_in[11];
    const float* root2 = (const float*)d_in[12];
    const float* bias2 = (const float*)d_in[13];
    const float* bn1g  = (const float*)d_in[14];
    const float* bn1b  = (const float*)d_in[15];
    const float* bn1m  = (const float*)d_in[16];
    const float* bn1v  = (const float*)d_in[17];
    const float* bn2g  = (const float*)d_in[18];
    const float* bn2b  = (const float*)d_in[19];
    const float* bn2m  = (const float*)d_in[20];
    const float* bn2v  = (const float*)d_in[21];
    const float* r1w   = (const float*)d_in[22];
    const float* r1b   = (const float*)d_in[23];
    const float* r2w   = (const float*)d_in[24];
    const float* r2b   = (const float*)d_in[25];
    const int*   eidx  = (const int*)d_in[26];
    const int*   batch = (const int*)d_in[27];
    float* out = (float*)d_out;

    float* p_h1 = nullptr;
    cudaGetSymbolAddress((void**)&p_h1, g_h1);

    const int THR = 256;
    const int gNC = (Nn * Cc + THR - 1) / THR;        // 1250 blocks
    const int gE  = (Ee + THR - 1) / THR;
    const int gEW = (Ee / 2 * 32 + THR - 1) / THR;    // 2 edges per warp: 6250 blocks

    k_deg<<<gE, THR>>>(eidx);

    // layer 1
    k_xb<<<gNC, THR>>>(x, e1b2);
    k_T<<<148, 512>>>(x, e1w2);
    k_edge<<<gEW, THR>>>(ea, eidx, e1w1, e1b1);
    k_node1<<<gNC, THR>>>(x, root1, bias1, bn1g, bn1b, bn1m, bn1v, p_h1);

    // layer 2
    k_xb<<<gNC, THR>>>(p_h1, e2b2);
    k_T<<<148, 512>>>(p_h1, e2w2);
    k_edge<<<gEW, THR>>>(ea, eidx, e2w1, e2b1);
    k_node2<<<gNC, THR>>>(p_h1, root2, bias2, bn2g, bn2b, bn2m, bn2v, batch);

    // readout (pool already scattered by k_node2)
    k_readout<<<1, 64>>>(r1w, r1b, r2w, r2b, out);
}

// round 7
// speedup vs baseline: 1.3155x; 1.0562x over previous
#include <cuda_runtime.h>
#include <cuda_fp16.h>

#define Nn 10000
#define Ee 100000
#define Cc 32
#define Gg 64
#define BN_EPS 1e-5f

typedef unsigned long long u64;

// ---- scratch (static device globals; zero-initialized at load) ----
// T2[n][kp][op]: u64 = {half2(T[2kp][2op],T[2kp][2op+1]), half2(T[2kp+1][2op],T[2kp+1][2op+1])}
__device__ u64   g_T2[(size_t)Nn * 256];      // 20.48 MB
__device__ float g_xb[Nn * Cc];               // b2 contribution per node
__device__ float g_agg[Nn * Cc];              // scatter-sum accumulator (reset in k_node)
__device__ float g_h1[Nn * Cc];               // layer-1 output
__device__ float g_deg[Nn];                   // in-degree by dst (reset in node2)
__device__ float g_pool[Gg * Cc];             // (reset in readout)
__device__ float g_pcnt[Gg];                  // (reset in readout)

// packed f32x2 helpers (sm_100+; ptxas will not auto-fuse)
__device__ __forceinline__ void fma2(u64& d, u64 a, u64 b) {
    asm("fma.rn.f32x2 %0, %1, %2, %0;" : "+l"(d) : "l"(a), "l"(b));
}
__device__ __forceinline__ u64 pack2(float lo, float hi) {
    u64 r;
    asm("mov.b64 %0, {%1, %2};" : "=l"(r) : "f"(lo), "f"(hi));
    return r;
}
__device__ __forceinline__ float2 unpack2(u64 v) {
    float2 r;
    asm("mov.b64 {%0, %1}, %2;" : "=f"(r.x), "=f"(r.y) : "l"(v));
    return r;
}
__device__ __forceinline__ void red_add_v2(float* addr, float a, float b) {
    asm volatile("red.global.add.v2.f32 [%0], {%1, %2};"
                 :: "l"(addr), "f"(a), "f"(b) : "memory");
}

// ---- in-degree by dst ----
__global__ void k_deg(const int* __restrict__ ei) {
    int e = blockIdx.x * blockDim.x + threadIdx.x;
    if (e < Ee) atomicAdd(&g_deg[ei[Ee + e]], 1.f);
}

// ---- xb[n,o] = sum_i x[n,i] * b2[i*C+o] ----
__global__ void k_xb(const float* __restrict__ x, const float* __restrict__ b2) {
    int t = blockIdx.x * blockDim.x + threadIdx.x;
    if (t >= Nn * Cc) return;
    int n = t >> 5, o = t & 31;
    const float* xr = x + n * Cc;
    float a0 = 0.f, a1 = 0.f;
#pragma unroll
    for (int i = 0; i < Cc; i += 2) {
        a0 += __ldg(&xr[i])     * b2[i * Cc + o];
        a1 += __ldg(&xr[i + 1]) * b2[(i + 1) * Cc + o];
    }
    g_xb[t] = a0 + a1;
}

// ---- T[n,k,o] = sum_i x[n,i] * w2[k, i*C+o], fp16, (kpair, opair) u64 layout ----
// 512 threads: kp = tid>>5 (0..15); o = tid&31 (warp per kp).
__global__ void __launch_bounds__(512, 1)
k_T(const float* __restrict__ x, const float* __restrict__ w2) {
    int kp = threadIdx.x >> 5, o = threadIdx.x & 31;

    // w[i] = (w2[2kp, i*32+o], w2[2kp+1, i*32+o]) packed
    u64 w[32];
    const float* wa = w2 + (2 * kp) * 1024 + o;
    const float* wb = w2 + (2 * kp + 1) * 1024 + o;
#pragma unroll
    for (int i = 0; i < 32; i++) w[i] = pack2(__ldg(&wa[i * 32]), __ldg(&wb[i * 32]));

    __shared__ u64 xs2[32][32];        // splat tile: xs2[j][i] = (x[nb+j,i], x[nb+j,i])

    int npb = (Nn + gridDim.x - 1) / gridDim.x;
    int n0 = blockIdx.x * npb;
    int n1 = min(n0 + npb, Nn);
    for (int nb = n0; nb < n1; nb += 32) {
        int cnt = min(32, n1 - nb);
#pragma unroll
        for (int r = 0; r < 2; r++) {
            int idx = threadIdx.x + r * 512;
            int jl = idx >> 5, il = idx & 31;
            float v = (nb + jl < n1) ? x[(nb + jl) * 32 + il] : 0.f;
            xs2[jl][il] = pack2(v, v);
        }
        __syncthreads();
        for (int j = 0; j < cnt; j++) {
            const u64* row = xs2[j];
            u64 a0 = 0ull, a1 = 0ull;
#pragma unroll
            for (int i = 0; i < 32; i += 2) {
                fma2(a0, w[i],     row[i]);
                fma2(a1, w[i + 1], row[i + 1]);
            }
            float2 fa = unpack2(a0), fb = unpack2(a1);
            float r0 = fa.x + fb.x;            // T[2kp][o]
            float r1 = fa.y + fb.y;            // T[2kp+1][o]
            float s0 = __shfl_down_sync(0xffffffffu, r0, 1);
            float s1 = __shfl_down_sync(0xffffffffu, r1, 1);
            if (!(o & 1)) {
                __half2 lo = __floats2half2_rn(r0, s0);   // k=2kp:   (o, o+1)
                __half2 hi = __floats2half2_rn(r1, s1);   // k=2kp+1: (o, o+1)
                u64 payload = ((u64)*(unsigned*)&hi << 32) | *(unsigned*)&lo;
                g_T2[(size_t)(nb + j) * 256 + kp * 16 + (o >> 1)] = payload;
            }
        }
        __syncthreads();
    }
}

// ---- edge kernel: 2 edges per warp IN PARALLEL (half-warp each), lane = o-pair ----
__global__ void k_edge(const float* __restrict__ ea, const int* __restrict__ ei,
                       const float* __restrict__ w1, const float* __restrict__ b1) {
    int wrp = (blockIdx.x * blockDim.x + threadIdx.x) >> 5;
    if (wrp >= Ee / 2) return;
    int lane = threadIdx.x & 31;
    int grp = lane >> 4;               // 0 -> edge 2w, 1 -> edge 2w+1
    int l = lane & 15;                 // o-pair index: o = 2l, 2l+1
    int e = 2 * wrp + grp;
    int src = __ldg(&ei[e]);
    int dst = __ldg(&ei[Ee + e]);
    float4 a = __ldg((const float4*)ea + e);

    // h for hidden units 2l, 2l+1 (this lane holds h[2l], h[2l+1])
    float2 w0 = __ldg((const float2*)(w1 + 0 * 32 + 2 * l));
    float2 w1r = __ldg((const float2*)(w1 + 1 * 32 + 2 * l));
    float2 w2r = __ldg((const float2*)(w1 + 2 * 32 + 2 * l));
    float2 w3r = __ldg((const float2*)(w1 + 3 * 32 + 2 * l));
    float2 bv = __ldg((const float2*)(b1 + 2 * l));
    float h_lo = fmaxf(bv.x + a.x * w0.x + a.y * w1r.x + a.z * w2r.x + a.w * w3r.x, 0.f);
    float h_hi = fmaxf(bv.y + a.x * w0.y + a.y * w1r.y + a.z * w2r.y + a.w * w3r.y, 0.f);

    float2 xbv = __ldg((const float2*)(g_xb + src * 32 + 2 * l));
    const u64* Tp = g_T2 + (size_t)src * 256 + l;

    float ax = 0.f, ay = 0.f, bx = 0.f, by = 0.f;   // 4 independent chains
    int base = lane & 16;
#pragma unroll
    for (int kp = 0; kp < 16; kp++) {
        float hA = __shfl_sync(0xffffffffu, h_lo, base + kp);   // h[2kp]
        float hB = __shfl_sync(0xffffffffu, h_hi, base + kp);   // h[2kp+1]
        u64 t = __ldg(&Tp[kp * 16]);
        unsigned ulo = (unsigned)t, uhi = (unsigned)(t >> 32);
        float2 flo = __half22float2(*(__half2*)&ulo);           // k=2kp:   (o, o+1)
        float2 fhi = __half22float2(*(__half2*)&uhi);           // k=2kp+1: (o, o+1)
        ax += hA * flo.x;  ay += hA * flo.y;
        bx += hB * fhi.x;  by += hB * fhi.y;
    }
    red_add_v2(&g_agg[dst * 32 + 2 * l], xbv.x + ax + bx, xbv.y + ay + by);
}

// ---- node update layer 1: mean-agg + root + bias + BN + ReLU; resets agg ----
__global__ void k_node1(const float* __restrict__ xin, const float* __restrict__ root,
                        const float* __restrict__ bias,
                        const float* __restrict__ bg, const float* __restrict__ bb,
                        const float* __restrict__ bm, const float* __restrict__ bv,
                        float* __restrict__ out) {
    int t = blockIdx.x * blockDim.x + threadIdx.x;
    if (t >= Nn * Cc) return;
    int n = t >> 5, o = t & 31;
    float val = g_agg[t] / fmaxf(g_deg[n], 1.f);
    g_agg[t] = 0.f;                                  // reset for layer 2
    const float* xr = xin + n * Cc;
    float a0 = 0.f, a1 = 0.f;
#pragma unroll
    for (int i = 0; i < Cc; i += 2) {
        a0 += __ldg(&xr[i])     * root[i * Cc + o];
        a1 += __ldg(&xr[i + 1]) * root[(i + 1) * Cc + o];
    }
    val += a0 + a1 + bias[o];
    val = (val - bm[o]) * rsqrtf(bv[o] + BN_EPS) * bg[o] + bb[o];
    out[t] = fmaxf(val, 0.f);
}

// ---- node update layer 2 + fused mean-pool scatter; resets agg & deg ----
__global__ void k_node2(const float* __restrict__ xin, const float* __restrict__ root,
                        const float* __restrict__ bias,
                        const float* __restrict__ bg, const float* __restrict__ bb,
                        const float* __restrict__ bm, const float* __restrict__ bv,
                        const int* __restrict__ batch) {
    int t = blockIdx.x * blockDim.x + threadIdx.x;
    if (t >= Nn * Cc) return;
    int n = t >> 5, o = t & 31;
    float dg = g_deg[n];
    float val = g_agg[t] / fmaxf(dg, 1.f);
    g_agg[t] = 0.f;                                  // reset for next replay
    __syncwarp();
    if (o == 0) g_deg[n] = 0.f;                      // all readers of deg[n] are this warp
    const float* xr = xin + n * Cc;
    float a0 = 0.f, a1 = 0.f;
#pragma unroll
    for (int i = 0; i < Cc; i += 2) {
        a0 += __ldg(&xr[i])     * root[i * Cc + o];
        a1 += __ldg(&xr[i + 1]) * root[(i + 1) * Cc + o];
    }
    val += a0 + a1 + bias[o];
    val = (val - bm[o]) * rsqrtf(bv[o] + BN_EPS) * bg[o] + bb[o];
    val = fmaxf(val, 0.f);
    int gph = __ldg(&batch[n]);
    atomicAdd(&g_pool[gph * Cc + o], val);
    if (o == 0) atomicAdd(&g_pcnt[gph], 1.f);
}

// ---- readout MLP; resets pool/pcnt ----
__global__ void k_readout(const float* __restrict__ r1w, const float* __restrict__ r1b,
                          const float* __restrict__ r2w, const float* __restrict__ r2b,
                          float* __restrict__ out) {
    int gph = blockIdx.x * blockDim.x + threadIdx.x;
    if (gph >= Gg) return;
    float c = fmaxf(g_pcnt[gph], 1.f);
    float p[Cc];
#pragma unroll
    for (int o = 0; o < Cc; o++) p[o] = g_pool[gph * Cc + o] / c;
    float res = r2b[0];
#pragma unroll
    for (int j = 0; j < 16; j++) {
        float hid = r1b[j];
#pragma unroll
        for (int o = 0; o < Cc; o++) hid += p[o] * r1w[o * 16 + j];
        res += fmaxf(hid, 0.f) * r2w[j];
    }
    out[gph] = res;
    // reset pooled state for next replay
#pragma unroll
    for (int o = 0; o < Cc; o++) g_pool[gph * Cc + o] = 0.f;
    g_pcnt[gph] = 0.f;
}

extern "C" void kernel_launch(void* const* d_in, const int* in_sizes, int n_in,
                              void* d_out, int out_size) {
    const float* x     = (const float*)d_in[0];
    const float* ea    = (const float*)d_in[1];
    const float* e1w1  = (const float*)d_in[2];
    const float* e1b1  = (const float*)d_in[3];
    const float* e1w2  = (const float*)d_in[4];
    const float* e1b2  = (const float*)d_in[5];
    const float* root1 = (const float*)d_in[6];
    const float* bias1 = (const float*)d_in[7];
    const float* e2w1  = (const float*)d_in[8];
    const float* e2b1  = (const float*)d_in[9];
    const float* e2w2  = (const float*)d_in[10];
    const float* e2b2  = (const float*)d_in[11];
    const float* root2 = (const float*)d_in[12];
    const float* bias2 = (const float*)d_in[13];
    const float* bn1g  = (const float*)d_in[14];
    const float* bn1b  = (const float*)d_in[15];
    const float* bn1m  = (const float*)d_in[16];
    const float* bn1v  = (const float*)d_in[17];
    const float* bn2g  = (const float*)d_in[18];
    const float* bn2b  = (const float*)d_in[19];
    const float* bn2m  = (const float*)d_in[20];
    const float* bn2v  = (const float*)d_in[21];
    const float* r1w   = (const float*)d_in[22];
    const float* r1b   = (const float*)d_in[23];
    const float* r2w   = (const float*)d_in[24];
    const float* r2b   = (const float*)d_in[25];
    const int*   eidx  = (const int*)d_in[26];
    const int*   batch = (const int*)d_in[27];
    float* out = (float*)d_out;

    float* p_h1 = nullptr;
    cudaGetSymbolAddress((void**)&p_h1, g_h1);

    const int THR = 256;
    const int gNC = (Nn * Cc + THR - 1) / THR;        // 1250 blocks
    const int gE  = (Ee + THR - 1) / THR;
    const int gEW = (Ee / 2 * 32 + THR - 1) / THR;    // 2 parallel edges per warp

    k_deg<<<gE, THR>>>(eidx);

    // layer 1
    k_xb<<<gNC, THR>>>(x, e1b2);
    k_T<<<148, 512>>>(x, e1w2);
    k_edge<<<gEW, THR>>>(ea, eidx, e1w1, e1b1);
    k_node1<<<gNC, THR>>>(x, root1, bias1, bn1g, bn1b, bn1m, bn1v, p_h1);

    // layer 2
    k_xb<<<gNC, THR>>>(p_h1, e2b2);
    k_T<<<148, 512>>>(p_h1, e2w2);
    k_edge<<<gEW, THR>>>(ea, eidx, e2w1, e2b1);
    k_node2<<<gNC, THR>>>(p_h1, root2, bias2, bn2g, bn2b, bn2m, bn2v, batch);

    // readout (pool already scattered by k_node2)
    k_readout<<<1, 64>>>(r1w, r1b, r2w, r2b, out);
}

// round 8
// speedup vs baseline: 1.7962x; 1.3655x over previous
#include <cuda_runtime.h>
#include <cuda_fp16.h>

#define Nn 10000
#define Ee 100000
#define Cc 32
#define Gg 64
#define BN_EPS 1e-5f

typedef unsigned long long u64;
typedef unsigned int u32;

// ---- scratch (static device globals; zero-initialized at load) ----
// T2[n][kp][op]: u64 = {half2(T[2kp][2op],T[2kp][2op+1]), half2(T[2kp+1][2op],T[2kp+1][2op+1])}
__device__ u64   g_T2[(size_t)Nn * 256];      // 20.48 MB
__device__ float g_xb[Nn * Cc];               // b2 contribution per node
__device__ float g_agg[Nn * Cc];              // scatter-sum accumulator (reset in k_node)
__device__ float g_h1[Nn * Cc];               // layer-1 output
__device__ float g_deg[Nn];                   // in-degree by dst (reset in node2)
__device__ float g_pool[Gg * Cc];             // (reset in readout)
__device__ float g_pcnt[Gg];                  // (reset in readout)

__device__ __forceinline__ void red_add_v2(float* addr, float a, float b) {
    asm volatile("red.global.add.v2.f32 [%0], {%1, %2};"
                 :: "l"(addr), "f"(a), "f"(b) : "memory");
}
__device__ __forceinline__ u32 h2pack(float lo, float hi) {
    __half2 h = __floats2half2_rn(lo, hi);
    return *(u32*)&h;
}
__device__ __forceinline__ void mma16816(float c[4], u32 a0, u32 a1, u32 a2, u32 a3,
                                         u32 b0, u32 b1) {
    asm("mma.sync.aligned.m16n8k16.row.col.f32.f16.f16.f32 "
        "{%0,%1,%2,%3}, {%4,%5,%6,%7}, {%8,%9}, {%0,%1,%2,%3};"
        : "+f"(c[0]), "+f"(c[1]), "+f"(c[2]), "+f"(c[3])
        : "r"(a0), "r"(a1), "r"(a2), "r"(a3), "r"(b0), "r"(b1));
}

// ---- in-degree by dst ----
__global__ void k_deg(const int* __restrict__ ei) {
    int e = blockIdx.x * blockDim.x + threadIdx.x;
    if (e < Ee) atomicAdd(&g_deg[ei[Ee + e]], 1.f);
}

// ---- k_T: T[n][k][o] = sum_i x[n,i] * w2[k, i*32+o] via HMMA; also xb = x@b2 fused ----
// 512 threads = 16 warps; warp w owns kp=w (k = 2w, 2w+1), loops oc=0..3 (o-octet).
// 625 tiles of 16 nodes (exactly 10000). B fragments register-resident per warp.
__global__ void __launch_bounds__(512, 1)
k_T(const float* __restrict__ x, const float* __restrict__ w2,
    const float* __restrict__ b2) {
    int lane = threadIdx.x & 31;
    int w = threadIdx.x >> 5;          // = kp
    int tg = lane & 3;                 // thread-in-group (cols)
    int gr = lane >> 2;                // group (rows / n)

    // ---- load B fragments for w2: Bf[q][kk][step][reg] ----
    u32 Bf[4][2][2][2];
#pragma unroll
    for (int q = 0; q < 4; q++)
#pragma unroll
        for (int kk = 0; kk < 2; kk++) {
            const float* rb = w2 + (2 * w + kk) * 1024 + q * 8 + gr;
#pragma unroll
            for (int st = 0; st < 2; st++) {
                int i0 = 2 * tg + 16 * st;
                Bf[q][kk][st][0] = h2pack(__ldg(&rb[i0 * 32]),       __ldg(&rb[(i0 + 1) * 32]));
                Bf[q][kk][st][1] = h2pack(__ldg(&rb[(i0 + 8) * 32]), __ldg(&rb[(i0 + 9) * 32]));
            }
        }
    // ---- B fragments for b2 (warps 0..3 only; warp w handles o-octet w) ----
    u32 Bb[2][2];
    if (w < 4) {
        const float* rb = b2 + w * 8 + gr;
#pragma unroll
        for (int st = 0; st < 2; st++) {
            int i0 = 2 * tg + 16 * st;
            Bb[st][0] = h2pack(__ldg(&rb[i0 * 32]),       __ldg(&rb[(i0 + 1) * 32]));
            Bb[st][1] = h2pack(__ldg(&rb[(i0 + 8) * 32]), __ldg(&rb[(i0 + 9) * 32]));
        }
    }

    __shared__ __half xs[16 * 40];     // 16 nodes x 32 (stride 40 halves: conflict-free)

    for (int tile = blockIdx.x; tile < 625; tile += gridDim.x) {
        int nb = tile * 16;
        __syncthreads();
        {   // fill x tile as fp16 (512 elements, one per thread)
            int j = threadIdx.x >> 5, i = threadIdx.x & 31;
            xs[j * 40 + i] = __float2half(x[(nb + j) * 32 + i]);
        }
        __syncthreads();

        // A fragments (shared by all q): 8 x LDS.32
        const u32* xp = (const u32*)xs;
        int ab = gr * 20 + tg;         // u32 index: row gr, halves 2*tg
        u32 a0 = xp[ab],            a1 = xp[ab + 160];
        u32 a2 = xp[ab + 4],        a3 = xp[ab + 164];
        u32 a4 = xp[ab + 8],        a5 = xp[ab + 168];
        u32 a6 = xp[ab + 12],       a7 = xp[ab + 172];

#pragma unroll
        for (int q = 0; q < 4; q++) {
            float c[4] = {0.f, 0.f, 0.f, 0.f};   // k = 2w
            float d[4] = {0.f, 0.f, 0.f, 0.f};   // k = 2w+1
            mma16816(c, a0, a1, a2, a3, Bf[q][0][0][0], Bf[q][0][0][1]);
            mma16816(c, a4, a5, a6, a7, Bf[q][0][1][0], Bf[q][0][1][1]);
            mma16816(d, a0, a1, a2, a3, Bf[q][1][0][0], Bf[q][1][0][1]);
            mma16816(d, a4, a5, a6, a7, Bf[q][1][1][0], Bf[q][1][1][1]);
            // pack: node gr -> (c0,c1|d0,d1), node gr+8 -> (c2,c3|d2,d3)
            u64 p0 = ((u64)h2pack(d[0], d[1]) << 32) | h2pack(c[0], c[1]);
            u64 p1 = ((u64)h2pack(d[2], d[3]) << 32) | h2pack(c[2], c[3]);
            size_t op = q * 4 + tg;
            g_T2[(size_t)(nb + gr)     * 256 + w * 16 + op] = p0;
            g_T2[(size_t)(nb + gr + 8) * 256 + w * 16 + op] = p1;
        }
        if (w < 4) {                   // fused xb = x @ b2 (o-octet w)
            float c[4] = {0.f, 0.f, 0.f, 0.f};
            mma16816(c, a0, a1, a2, a3, Bb[0][0], Bb[0][1]);
            mma16816(c, a4, a5, a6, a7, Bb[1][0], Bb[1][1]);
            int o = w * 8 + 2 * tg;
            *(float2*)(g_xb + (nb + gr)     * 32 + o) = make_float2(c[0], c[1]);
            *(float2*)(g_xb + (nb + gr + 8) * 32 + o) = make_float2(c[2], c[3]);
        }
    }
}

// ---- edge kernel: 2 edges per warp IN PARALLEL (half-warp each), lane = o-pair ----
__global__ void k_edge(const float* __restrict__ ea, const int* __restrict__ ei,
                       const float* __restrict__ w1, const float* __restrict__ b1) {
    int wrp = (blockIdx.x * blockDim.x + threadIdx.x) >> 5;
    if (wrp >= Ee / 2) return;
    int lane = threadIdx.x & 31;
    int grp = lane >> 4;               // 0 -> edge 2w, 1 -> edge 2w+1
    int l = lane & 15;                 // o-pair index: o = 2l, 2l+1
    int e = 2 * wrp + grp;
    int src = __ldg(&ei[e]);
    int dst = __ldg(&ei[Ee + e]);
    float4 a = __ldg((const float4*)ea + e);

    float2 w0 = __ldg((const float2*)(w1 + 0 * 32 + 2 * l));
    float2 w1r = __ldg((const float2*)(w1 + 1 * 32 + 2 * l));
    float2 w2r = __ldg((const float2*)(w1 + 2 * 32 + 2 * l));
    float2 w3r = __ldg((const float2*)(w1 + 3 * 32 + 2 * l));
    float2 bv = __ldg((const float2*)(b1 + 2 * l));
    float h_lo = fmaxf(bv.x + a.x * w0.x + a.y * w1r.x + a.z * w2r.x + a.w * w3r.x, 0.f);
    float h_hi = fmaxf(bv.y + a.x * w0.y + a.y * w1r.y + a.z * w2r.y + a.w * w3r.y, 0.f);

    float2 xbv = __ldg((const float2*)(g_xb + src * 32 + 2 * l));
    const u64* Tp = g_T2 + (size_t)src * 256 + l;

    float ax = 0.f, ay = 0.f, bx = 0.f, by = 0.f;
    int base = lane & 16;
#pragma unroll
    for (int kp = 0; kp < 16; kp++) {
        float hA = __shfl_sync(0xffffffffu, h_lo, base + kp);
        float hB = __shfl_sync(0xffffffffu, h_hi, base + kp);
        u64 t = __ldg(&Tp[kp * 16]);
        unsigned ulo = (unsigned)t, uhi = (unsigned)(t >> 32);
        float2 flo = __half22float2(*(__half2*)&ulo);
        float2 fhi = __half22float2(*(__half2*)&uhi);
        ax += hA * flo.x;  ay += hA * flo.y;
        bx += hB * fhi.x;  by += hB * fhi.y;
    }
    red_add_v2(&g_agg[dst * 32 + 2 * l], xbv.x + ax + bx, xbv.y + ay + by);
}

// ---- node update layer 1: mean-agg + root + bias + BN + ReLU; resets agg ----
__global__ void k_node1(const float* __restrict__ xin, const float* __restrict__ root,
                        const float* __restrict__ bias,
                        const float* __restrict__ bg, const float* __restrict__ bb,
                        const float* __restrict__ bm, const float* __restrict__ bv,
                        float* __restrict__ out) {
    int t = blockIdx.x * blockDim.x + threadIdx.x;
    if (t >= Nn * Cc) return;
    int n = t >> 5, o = t & 31;
    float val = g_agg[t] / fmaxf(g_deg[n], 1.f);
    g_agg[t] = 0.f;
    const float* xr = xin + n * Cc;
    float a0 = 0.f, a1 = 0.f;
#pragma unroll
    for (int i = 0; i < Cc; i += 2) {
        a0 += __ldg(&xr[i])     * root[i * Cc + o];
        a1 += __ldg(&xr[i + 1]) * root[(i + 1) * Cc + o];
    }
    val += a0 + a1 + bias[o];
    val = (val - bm[o]) * rsqrtf(bv[o] + BN_EPS) * bg[o] + bb[o];
    out[t] = fmaxf(val, 0.f);
}

// ---- node update layer 2 + fused mean-pool scatter; resets agg & deg ----
__global__ void k_node2(const float* __restrict__ xin, const float* __restrict__ root,
                        const float* __restrict__ bias,
                        const float* __restrict__ bg, const float* __restrict__ bb,
                        const float* __restrict__ bm, const float* __restrict__ bv,
                        const int* __restrict__ batch) {
    int t = blockIdx.x * blockDim.x + threadIdx.x;
    if (t >= Nn * Cc) return;
    int n = t >> 5, o = t & 31;
    float dg = g_deg[n];
    float val = g_agg[t] / fmaxf(dg, 1.f);
    g_agg[t] = 0.f;
    __syncwarp();
    if (o == 0) g_deg[n] = 0.f;
    const float* xr = xin + n * Cc;
    float a0 = 0.f, a1 = 0.f;
#pragma unroll
    for (int i = 0; i < Cc; i += 2) {
        a0 += __ldg(&xr[i])     * root[i * Cc + o];
        a1 += __ldg(&xr[i + 1]) * root[(i + 1) * Cc + o];
    }
    val += a0 + a1 + bias[o];
    val = (val - bm[o]) * rsqrtf(bv[o] + BN_EPS) * bg[o] + bb[o];
    val = fmaxf(val, 0.f);
    int gph = __ldg(&batch[n]);
    atomicAdd(&g_pool[gph * Cc + o], val);
    if (o == 0) atomicAdd(&g_pcnt[gph], 1.f);
}

// ---- readout MLP; resets pool/pcnt ----
__global__ void k_readout(const float* __restrict__ r1w, const float* __restrict__ r1b,
                          const float* __restrict__ r2w, const float* __restrict__ r2b,
                          float* __restrict__ out) {
    int gph = blockIdx.x * blockDim.x + threadIdx.x;
    if (gph >= Gg) return;
    float c = fmaxf(g_pcnt[gph], 1.f);
    float p[Cc];
#pragma unroll
    for (int o = 0; o < Cc; o++) p[o] = g_pool[gph * Cc + o] / c;
    float res = r2b[0];
#pragma unroll
    for (int j = 0; j < 16; j++) {
        float hid = r1b[j];
#pragma unroll
        for (int o = 0; o < Cc; o++) hid += p[o] * r1w[o * 16 + j];
        res += fmaxf(hid, 0.f) * r2w[j];
    }
    out[gph] = res;
#pragma unroll
    for (int o = 0; o < Cc; o++) g_pool[gph * Cc + o] = 0.f;
    g_pcnt[gph] = 0.f;
}

extern "C" void kernel_launch(void* const* d_in, const int* in_sizes, int n_in,
                              void* d_out, int out_size) {
    const float* x     = (const float*)d_in[0];
    const float* ea    = (const float*)d_in[1];
    const float* e1w1  = (const float*)d_in[2];
    const float* e1b1  = (const float*)d_in[3];
    const float* e1w2  = (const float*)d_in[4];
    const float* e1b2  = (const float*)d_in[5];
    const float* root1 = (const float*)d_in[6];
    const float* bias1 = (const float*)d_in[7];
    const float* e2w1  = (const float*)d_in[8];
    const float* e2b1  = (const float*)d_in[9];
    const float* e2w2  = (const float*)d_in[10];
    const float* e2b2  = (const float*)d_in[11];
    const float* root2 = (const float*)d_in[12];
    const float* bias2 = (const float*)d_in[13];
    const float* bn1g  = (const float*)d_in[14];
    const float* bn1b  = (const float*)d_in[15];
    const float* bn1m  = (const float*)d_in[16];
    const float* bn1v  = (const float*)d_in[17];
    const float* bn2g  = (const float*)d_in[18];
    const float* bn2b  = (const float*)d_in[19];
    const float* bn2m  = (const float*)d_in[20];
    const float* bn2v  = (const float*)d_in[21];
    const float* r1w   = (const float*)d_in[22];
    const float* r1b   = (const float*)d_in[23];
    const float* r2w   = (const float*)d_in[24];
    const float* r2b   = (const float*)d_in[25];
    const int*   eidx  = (const int*)d_in[26];
    const int*   batch = (const int*)d_in[27];
    float* out = (float*)d_out;

    float* p_h1 = nullptr;
    cudaGetSymbolAddress((void**)&p_h1, g_h1);

    const int THR = 256;
    const int gNC = (Nn * Cc + THR - 1) / THR;        // 1250 blocks
    const int gE  = (Ee + THR - 1) / THR;
    const int gEW = (Ee / 2 * 32 + THR - 1) / THR;    // 2 parallel edges per warp

    k_deg<<<gE, THR>>>(eidx);

    // layer 1 (k_T also computes xb)
    k_T<<<148, 512>>>(x, e1w2, e1b2);
    k_edge<<<gEW, THR>>>(ea, eidx, e1w1, e1b1);
    k_node1<<<gNC, THR>>>(x, root1, bias1, bn1g, bn1b, bn1m, bn1v, p_h1);

    // layer 2
    k_T<<<148, 512>>>(p_h1, e2w2, e2b2);
    k_edge<<<gEW, THR>>>(ea, eidx, e2w1, e2b1);
    k_node2<<<gNC, THR>>>(p_h1, root2, bias2, bn2g, bn2b, bn2m, bn2v, batch);

    // readout
    k_readout<<<1, 64>>>(r1w, r1b, r2w, r2b, out);
}

// round 9
// speedup vs baseline: 2.0701x; 1.1525x over previous
#include <cuda_runtime.h>
#include <cuda_fp16.h>

#define Nn 10000
#define Ee 100000
#define Cc 32
#define Gg 64
#define BN_EPS 1e-5f

typedef unsigned long long u64;
typedef unsigned int u32;

// ---- scratch (static device globals; zero-initialized at load) ----
// T2[n][kp][op] u64 = {h2(T[2kp][2op],T[2kp][2op+1]), h2(T[2kp+1][2op],T[2kp+1][2op+1])}
// adjacent op pairs form a 16B quad -> LDG.128 in k_edge
__device__ __align__(16) u64   g_T2[(size_t)Nn * 256];   // 20.48 MB
__device__ __align__(16) float g_xb[Nn * Cc];
__device__ __align__(16) float g_agg[Nn * Cc];
__device__ __align__(16) float g_h1[Nn * Cc];
__device__ float g_deg[Nn];
__device__ __align__(16) float g_pool[Gg * Cc];
__device__ float g_pcnt[Gg];

__device__ __forceinline__ void red_add_v2(float* addr, float a, float b) {
    asm volatile("red.global.add.v2.f32 [%0], {%1, %2};"
                 :: "l"(addr), "f"(a), "f"(b) : "memory");
}
__device__ __forceinline__ void red_add_v4(float* addr, float a, float b, float c, float d) {
    asm volatile("red.global.add.v4.f32 [%0], {%1, %2, %3, %4};"
                 :: "l"(addr), "f"(a), "f"(b), "f"(c), "f"(d) : "memory");
}
__device__ __forceinline__ u32 h2pack(float lo, float hi) {
    __half2 h = __floats2half2_rn(lo, hi);
    return *(u32*)&h;
}
__device__ __forceinline__ void mma16816(float c[4], u32 a0, u32 a1, u32 a2, u32 a3,
                                         u32 b0, u32 b1) {
    asm("mma.sync.aligned.m16n8k16.row.col.f32.f16.f16.f32 "
        "{%0,%1,%2,%3}, {%4,%5,%6,%7}, {%8,%9}, {%0,%1,%2,%3};"
        : "+f"(c[0]), "+f"(c[1]), "+f"(c[2]), "+f"(c[3])
        : "r"(a0), "r"(a1), "r"(a2), "r"(a3), "r"(b0), "r"(b1));
}

// ---- in-degree by dst ----
__global__ void k_deg(const int* __restrict__ ei) {
    int e = blockIdx.x * blockDim.x + threadIdx.x;
    if (e < Ee) atomicAdd(&g_deg[ei[Ee + e]], 1.f);
}

// ---- k_T: T = x @ w2 (per-k o-rows) via HMMA; xb = x @ b2 fused ----
__global__ void __launch_bounds__(512, 1)
k_T(const float* __restrict__ x, const float* __restrict__ w2,
    const float* __restrict__ b2) {
    int lane = threadIdx.x & 31;
    int w = threadIdx.x >> 5;          // = kp
    int tg = lane & 3;
    int gr = lane >> 2;

    u32 Bf[4][2][2][2];
#pragma unroll
    for (int q = 0; q < 4; q++)
#pragma unroll
        for (int kk = 0; kk < 2; kk++) {
            const float* rb = w2 + (2 * w + kk) * 1024 + q * 8 + gr;
#pragma unroll
            for (int st = 0; st < 2; st++) {
                int i0 = 2 * tg + 16 * st;
                Bf[q][kk][st][0] = h2pack(__ldg(&rb[i0 * 32]),       __ldg(&rb[(i0 + 1) * 32]));
                Bf[q][kk][st][1] = h2pack(__ldg(&rb[(i0 + 8) * 32]), __ldg(&rb[(i0 + 9) * 32]));
            }
        }
    u32 Bb[2][2];
    if (w < 4) {
        const float* rb = b2 + w * 8 + gr;
#pragma unroll
        for (int st = 0; st < 2; st++) {
            int i0 = 2 * tg + 16 * st;
            Bb[st][0] = h2pack(__ldg(&rb[i0 * 32]),       __ldg(&rb[(i0 + 1) * 32]));
            Bb[st][1] = h2pack(__ldg(&rb[(i0 + 8) * 32]), __ldg(&rb[(i0 + 9) * 32]));
        }
    }

    __shared__ __half xs[16 * 40];

    for (int tile = blockIdx.x; tile < 625; tile += gridDim.x) {
        int nb = tile * 16;
        __syncthreads();
        {
            int j = threadIdx.x >> 5, i = threadIdx.x & 31;
            xs[j * 40 + i] = __float2half(x[(nb + j) * 32 + i]);
        }
        __syncthreads();

        const u32* xp = (const u32*)xs;
        int ab = gr * 20 + tg;
        u32 a0 = xp[ab],       a1 = xp[ab + 160];
        u32 a2 = xp[ab + 4],   a3 = xp[ab + 164];
        u32 a4 = xp[ab + 8],   a5 = xp[ab + 168];
        u32 a6 = xp[ab + 12],  a7 = xp[ab + 172];

#pragma unroll
        for (int q = 0; q < 4; q++) {
            float c[4] = {0.f, 0.f, 0.f, 0.f};
            float d[4] = {0.f, 0.f, 0.f, 0.f};
            mma16816(c, a0, a1, a2, a3, Bf[q][0][0][0], Bf[q][0][0][1]);
            mma16816(c, a4, a5, a6, a7, Bf[q][0][1][0], Bf[q][0][1][1]);
            mma16816(d, a0, a1, a2, a3, Bf[q][1][0][0], Bf[q][1][0][1]);
            mma16816(d, a4, a5, a6, a7, Bf[q][1][1][0], Bf[q][1][1][1]);
            u64 p0 = ((u64)h2pack(d[0], d[1]) << 32) | h2pack(c[0], c[1]);
            u64 p1 = ((u64)h2pack(d[2], d[3]) << 32) | h2pack(c[2], c[3]);
            size_t op = q * 4 + tg;
            g_T2[(size_t)(nb + gr)     * 256 + w * 16 + op] = p0;
            g_T2[(size_t)(nb + gr + 8) * 256 + w * 16 + op] = p1;
        }
        if (w < 4) {
            float c[4] = {0.f, 0.f, 0.f, 0.f};
            mma16816(c, a0, a1, a2, a3, Bb[0][0], Bb[0][1]);
            mma16816(c, a4, a5, a6, a7, Bb[1][0], Bb[1][1]);
            int o = w * 8 + 2 * tg;
            *(float2*)(g_xb + (nb + gr)     * 32 + o) = make_float2(c[0], c[1]);
            *(float2*)(g_xb + (nb + gr + 8) * 32 + o) = make_float2(c[2], c[3]);
        }
    }
}

// ---- edge kernel: 4 edges per warp (8-lane quads), lane = o-quad; LDG.128 T, red.v4 ----
__global__ void k_edge(const float* __restrict__ ea, const int* __restrict__ ei,
                       const float* __restrict__ w1, const float* __restrict__ b1) {
    int wrp = (blockIdx.x * blockDim.x + threadIdx.x) >> 5;
    if (wrp >= Ee / 4) return;
    int lane = threadIdx.x & 31;
    int grp = lane >> 3;               // edge within quad
    int q = lane & 7;                  // o-quad: o = 4q..4q+3
    int e = 4 * wrp + grp;
    int src = __ldg(&ei[e]);
    int dst = __ldg(&ei[Ee + e]);
    float4 a = __ldg((const float4*)ea + e);

    // h[4q+j], j=0..3 for this edge
    float4 bv  = __ldg((const float4*)(b1 + 4 * q));
    float4 w0v = __ldg((const float4*)(w1 + 0 * 32 + 4 * q));
    float4 w1v = __ldg((const float4*)(w1 + 1 * 32 + 4 * q));
    float4 w2v = __ldg((const float4*)(w1 + 2 * 32 + 4 * q));
    float4 w3v = __ldg((const float4*)(w1 + 3 * 32 + 4 * q));
    float h0 = fmaxf(bv.x + a.x * w0v.x + a.y * w1v.x + a.z * w2v.x + a.w * w3v.x, 0.f);
    float h1 = fmaxf(bv.y + a.x * w0v.y + a.y * w1v.y + a.z * w2v.y + a.w * w3v.y, 0.f);
    float h2v = fmaxf(bv.z + a.x * w0v.z + a.y * w1v.z + a.z * w2v.z + a.w * w3v.z, 0.f);
    float h3 = fmaxf(bv.w + a.x * w0v.w + a.y * w1v.w + a.z * w2v.w + a.w * w3v.w, 0.f);

    float4 xbv = __ldg((const float4*)(g_xb + src * 32 + 4 * q));
    const uint4* Tp = (const uint4*)(g_T2 + (size_t)src * 256) + q;

    // accumulators: sA from even-k, sB from odd-k, per o in quad
    float sA0 = 0.f, sA1 = 0.f, sA2 = 0.f, sA3 = 0.f;
    float sB0 = 0.f, sB1 = 0.f, sB2 = 0.f, sB3 = 0.f;
    int base = lane & 24;
#pragma unroll
    for (int kp = 0; kp < 16; kp++) {
        int sl = base + (kp >> 1);
        float hA, hB;
        if ((kp & 1) == 0) {
            hA = __shfl_sync(0xffffffffu, h0, sl);   // h[2kp]
            hB = __shfl_sync(0xffffffffu, h1, sl);   // h[2kp+1]
        } else {
            hA = __shfl_sync(0xffffffffu, h2v, sl);
            hB = __shfl_sync(0xffffffffu, h3, sl);
        }
        uint4 t = __ldg(&Tp[kp * 8]);
        float2 f0 = __half22float2(*(__half2*)&t.x);   // k even, o 4q..4q+1
        float2 f1 = __half22float2(*(__half2*)&t.y);   // k odd,  o 4q..4q+1
        float2 f2 = __half22float2(*(__half2*)&t.z);   // k even, o 4q+2..4q+3
        float2 f3 = __half22float2(*(__half2*)&t.w);   // k odd,  o 4q+2..4q+3
        sA0 += hA * f0.x;  sA1 += hA * f0.y;  sA2 += hA * f2.x;  sA3 += hA * f2.y;
        sB0 += hB * f1.x;  sB1 += hB * f1.y;  sB2 += hB * f3.x;  sB3 += hB * f3.y;
    }
    red_add_v4(&g_agg[dst * 32 + 4 * q],
               xbv.x + sA0 + sB0, xbv.y + sA1 + sB1,
               xbv.z + sA2 + sB2, xbv.w + sA3 + sB3);
}

// ---- node update L1: o-pair threads, shfl x broadcast; resets agg ----
__global__ void k_node1(const float* __restrict__ xin, const float* __restrict__ root,
                        const float* __restrict__ bias,
                        const float* __restrict__ bg, const float* __restrict__ bb,
                        const float* __restrict__ bm, const float* __restrict__ bv,
                        float* __restrict__ out) {
    int t = blockIdx.x * blockDim.x + threadIdx.x;
    if (t >= Nn * 16) return;
    int n = t >> 4, l = t & 15;                 // o = 2l, 2l+1
    int lane = threadIdx.x & 31;
    int base = lane & 16;                       // half-warp owns one node

    float2 xv = __ldg((const float2*)(xin + n * 32 + 2 * l));
    float2 ag = *(const float2*)(g_agg + n * 32 + 2 * l);
    float dg = fmaxf(g_deg[n], 1.f);
    float vx = ag.x / dg, vy = ag.y / dg;
    *(float2*)(g_agg + n * 32 + 2 * l) = make_float2(0.f, 0.f);   // reset for layer 2

#pragma unroll
    for (int i = 0; i < 32; i++) {
        float xi = __shfl_sync(0xffffffffu, (i & 1) ? xv.y : xv.x, base + (i >> 1));
        float2 rv = __ldg((const float2*)(root + i * 32 + 2 * l));
        vx += xi * rv.x;  vy += xi * rv.y;
    }
    float2 bi = __ldg((const float2*)(bias + 2 * l));
    float2 m  = __ldg((const float2*)(bm + 2 * l));
    float2 v  = __ldg((const float2*)(bv + 2 * l));
    float2 g  = __ldg((const float2*)(bg + 2 * l));
    float2 be = __ldg((const float2*)(bb + 2 * l));
    vx = (vx + bi.x - m.x) * rsqrtf(v.x + BN_EPS) * g.x + be.x;
    vy = (vy + bi.y - m.y) * rsqrtf(v.y + BN_EPS) * g.y + be.y;
    *(float2*)(out + n * 32 + 2 * l) = make_float2(fmaxf(vx, 0.f), fmaxf(vy, 0.f));
}

// ---- node update L2 + fused mean-pool; resets agg & deg ----
__global__ void k_node2(const float* __restrict__ xin, const float* __restrict__ root,
                        const float* __restrict__ bias,
                        const float* __restrict__ bg, const float* __restrict__ bb,
                        const float* __restrict__ bm, const float* __restrict__ bv,
                        const int* __restrict__ batch) {
    int t = blockIdx.x * blockDim.x + threadIdx.x;
    if (t >= Nn * 16) return;
    int n = t >> 4, l = t & 15;
    int lane = threadIdx.x & 31;
    int base = lane & 16;

    float2 xv = __ldg((const float2*)(xin + n * 32 + 2 * l));
    float2 ag = *(const float2*)(g_agg + n * 32 + 2 * l);
    float dg = fmaxf(g_deg[n], 1.f);
    float vx = ag.x / dg, vy = ag.y / dg;
    *(float2*)(g_agg + n * 32 + 2 * l) = make_float2(0.f, 0.f);   // reset for next replay
    __syncwarp();
    if (l == 0) g_deg[n] = 0.f;

#pragma unroll
    for (int i = 0; i < 32; i++) {
        float xi = __shfl_sync(0xffffffffu, (i & 1) ? xv.y : xv.x, base + (i >> 1));
        float2 rv = __ldg((const float2*)(root + i * 32 + 2 * l));
        vx += xi * rv.x;  vy += xi * rv.y;
    }
    float2 bi = __ldg((const float2*)(bias + 2 * l));
    float2 m  = __ldg((const float2*)(bm + 2 * l));
    float2 v  = __ldg((const float2*)(bv + 2 * l));
    float2 g  = __ldg((const float2*)(bg + 2 * l));
    float2 be = __ldg((const float2*)(bb + 2 * l));
    vx = (vx + bi.x - m.x) * rsqrtf(v.x + BN_EPS) * g.x + be.x;
    vy = (vy + bi.y - m.y) * rsqrtf(v.y + BN_EPS) * g.y + be.y;
    vx = fmaxf(vx, 0.f);  vy = fmaxf(vy, 0.f);

    int gph = __ldg(&batch[n]);
    red_add_v2(&g_pool[gph * 32 + 2 * l], vx, vy);
    if (l == 0) atomicAdd(&g_pcnt[gph], 1.f);
}

// ---- readout MLP; resets pool/pcnt ----
__global__ void k_readout(const float* __restrict__ r1w, const float* __restrict__ r1b,
                          const float* __restrict__ r2w, const float* __restrict__ r2b,
                          float* __restrict__ out) {
    int gph = blockIdx.x * blockDim.x + threadIdx.x;
    if (gph >= Gg) return;
    float c = fmaxf(g_pcnt[gph], 1.f);
    float p[Cc];
#pragma unroll
    for (int o = 0; o < Cc; o++) p[o] = g_pool[gph * Cc + o] / c;
    float res = r2b[0];
#pragma unroll
    for (int j = 0; j < 16; j++) {
        float hid = r1b[j];
#pragma unroll
        for (int o = 0; o < Cc; o++) hid += p[o] * r1w[o * 16 + j];
        res += fmaxf(hid, 0.f) * r2w[j];
    }
    out[gph] = res;
#pragma unroll
    for (int o = 0; o < Cc; o++) g_pool[gph * Cc + o] = 0.f;
    g_pcnt[gph] = 0.f;
}

extern "C" void kernel_launch(void* const* d_in, const int* in_sizes, int n_in,
                              void* d_out, int out_size) {
    const float* x     = (const float*)d_in[0];
    const float* ea    = (const float*)d_in[1];
    const float* e1w1  = (const float*)d_in[2];
    const float* e1b1  = (const float*)d_in[3];
    const float* e1w2  = (const float*)d_in[4];
    const float* e1b2  = (const float*)d_in[5];
    const float* root1 = (const float*)d_in[6];
    const float* bias1 = (const float*)d_in[7];
    const float* e2w1  = (const float*)d_in[8];
    const float* e2b1  = (const float*)d_in[9];
    const float* e2w2  = (const float*)d_in[10];
    const float* e2b2  = (const float*)d_in[11];
    const float* root2 = (const float*)d_in[12];
    const float* bias2 = (const float*)d_in[13];
    const float* bn1g  = (const float*)d_in[14];
    const float* bn1b  = (const float*)d_in[15];
    const float* bn1m  = (const float*)d_in[16];
    const float* bn1v  = (const float*)d_in[17];
    const float* bn2g  = (const float*)d_in[18];
    const float* bn2b  = (const float*)d_in[19];
    const float* bn2m  = (const float*)d_in[20];
    const float* bn2v  = (const float*)d_in[21];
    const float* r1w   = (const float*)d_in[22];
    const float* r1b   = (const float*)d_in[23];
    const float* r2w   = (const float*)d_in[24];
    const float* r2b   = (const float*)d_in[25];
    const int*   eidx  = (const int*)d_in[26];
    const int*   batch = (const int*)d_in[27];
    float* out = (float*)d_out;

    float* p_h1 = nullptr;
    cudaGetSymbolAddress((void**)&p_h1, g_h1);

    const int THR = 256;
    const int gE   = (Ee + THR - 1) / THR;
    const int gEW  = (Ee / 4 * 32 + THR - 1) / THR;    // 4 edges/warp: 3125 blocks
    const int gN16 = (Nn * 16 + THR - 1) / THR;        // o-pair node threads: 625 blocks

    k_deg<<<gE, THR>>>(eidx);

    // layer 1 (k_T also computes xb)
    k_T<<<148, 512>>>(x, e1w2, e1b2);
    k_edge<<<gEW, THR>>>(ea, eidx, e1w1, e1b1);
    k_node1<<<gN16, THR>>>(x, root1, bias1, bn1g, bn1b, bn1m, bn1v, p_h1);

    // layer 2
    k_T<<<148, 512>>>(p_h1, e2w2, e2b2);
    k_edge<<<gEW, THR>>>(ea, eidx, e2w1, e2b1);
    k_node2<<<gN16, THR>>>(p_h1, root2, bias2, bn2g, bn2b, bn2m, bn2v, batch);

    // readout
    k_readout<<<1, 64>>>(r1w, r1b, r2w, r2b, out);
}

// round 10
// speedup vs baseline: 2.1739x; 1.0502x over previous
#include <cuda_runtime.h>
#include <cuda_fp16.h>

#define Nn 10000
#define Ee 100000
#define Cc 32
#define Gg 64
#define BN_EPS 1e-5f

typedef unsigned long long u64;
typedef unsigned int u32;

// ---- scratch (static device globals; zero-initialized at load) ----
// T2[n][kp][op] u64 = {h2(T[2kp][2op],T[2kp][2op+1]), h2(T[2kp+1][2op],T[2kp+1][2op+1])}
__device__ __align__(16) u64   g_T2[(size_t)Nn * 256];   // 20.48 MB
__device__ __align__(16) float g_xb[Nn * Cc];            // x @ b2
__device__ __align__(16) float g_xr[Nn * Cc];            // x @ root + bias
__device__ __align__(16) float g_agg[Nn * Cc];
__device__ __align__(16) float g_h1[Nn * Cc];
__device__ float g_deg[Nn];
__device__ __align__(16) float g_pool[Gg * Cc];
__device__ float g_pcnt[Gg];

__device__ __forceinline__ void red_add_v2(float* addr, float a, float b) {
    asm volatile("red.global.add.v2.f32 [%0], {%1, %2};"
                 :: "l"(addr), "f"(a), "f"(b) : "memory");
}
__device__ __forceinline__ void red_add_v4(float* addr, float a, float b, float c, float d) {
    asm volatile("red.global.add.v4.f32 [%0], {%1, %2, %3, %4};"
                 :: "l"(addr), "f"(a), "f"(b), "f"(c), "f"(d) : "memory");
}
__device__ __forceinline__ u32 h2pack(float lo, float hi) {
    __half2 h = __floats2half2_rn(lo, hi);
    return *(u32*)&h;
}
__device__ __forceinline__ void mma16816(float c[4], u32 a0, u32 a1, u32 a2, u32 a3,
                                         u32 b0, u32 b1) {
    asm("mma.sync.aligned.m16n8k16.row.col.f32.f16.f16.f32 "
        "{%0,%1,%2,%3}, {%4,%5,%6,%7}, {%8,%9}, {%0,%1,%2,%3};"
        : "+f"(c[0]), "+f"(c[1]), "+f"(c[2]), "+f"(c[3])
        : "r"(a0), "r"(a1), "r"(a2), "r"(a3), "r"(b0), "r"(b1));
}

// ---- k_T: T = x@w2 (HMMA) + xb = x@b2 (warps 0-3) + xr = x@root + bias (warps 4-7)
//      optional fused in-degree histogram (layer 1 only, overlaps tensor work) ----
__global__ void __launch_bounds__(512, 1)
k_T(const float* __restrict__ x, const float* __restrict__ w2,
    const float* __restrict__ b2, const float* __restrict__ root,
    const float* __restrict__ bias, const int* __restrict__ ei /* null = no deg */) {
    int lane = threadIdx.x & 31;
    int w = threadIdx.x >> 5;          // = kp
    int tg = lane & 3;
    int gr = lane >> 2;

    if (ei) {   // fused in-degree (layer 1): strided over all edges
        for (int e = blockIdx.x * 512 + threadIdx.x; e < Ee; e += gridDim.x * 512)
            atomicAdd(&g_deg[__ldg(&ei[Ee + e])], 1.f);
    }

    u32 Bf[4][2][2][2];
#pragma unroll
    for (int q = 0; q < 4; q++)
#pragma unroll
        for (int kk = 0; kk < 2; kk++) {
            const float* rb = w2 + (2 * w + kk) * 1024 + q * 8 + gr;
#pragma unroll
            for (int st = 0; st < 2; st++) {
                int i0 = 2 * tg + 16 * st;
                Bf[q][kk][st][0] = h2pack(__ldg(&rb[i0 * 32]),       __ldg(&rb[(i0 + 1) * 32]));
                Bf[q][kk][st][1] = h2pack(__ldg(&rb[(i0 + 8) * 32]), __ldg(&rb[(i0 + 9) * 32]));
            }
        }
    // side-matrix fragments: warps 0-3 -> b2 (octet w), warps 4-7 -> root (octet w-4)
    u32 Bs[2][2];
    float2 biasv = make_float2(0.f, 0.f);
    if (w < 8) {
        const float* src = (w < 4) ? (b2 + w * 8 + gr) : (root + (w - 4) * 8 + gr);
#pragma unroll
        for (int st = 0; st < 2; st++) {
            int i0 = 2 * tg + 16 * st;
            Bs[st][0] = h2pack(__ldg(&src[i0 * 32]),       __ldg(&src[(i0 + 1) * 32]));
            Bs[st][1] = h2pack(__ldg(&src[(i0 + 8) * 32]), __ldg(&src[(i0 + 9) * 32]));
        }
        if (w >= 4) biasv = __ldg((const float2*)(bias + (w - 4) * 8 + 2 * tg));
    }

    __shared__ __half xs[16 * 40];

    for (int tile = blockIdx.x; tile < 625; tile += gridDim.x) {
        int nb = tile * 16;
        __syncthreads();
        {
            int j = threadIdx.x >> 5, i = threadIdx.x & 31;
            xs[j * 40 + i] = __float2half(x[(nb + j) * 32 + i]);
        }
        __syncthreads();

        const u32* xp = (const u32*)xs;
        int ab = gr * 20 + tg;
        u32 a0 = xp[ab],       a1 = xp[ab + 160];
        u32 a2 = xp[ab + 4],   a3 = xp[ab + 164];
        u32 a4 = xp[ab + 8],   a5 = xp[ab + 168];
        u32 a6 = xp[ab + 12],  a7 = xp[ab + 172];

#pragma unroll
        for (int q = 0; q < 4; q++) {
            float c[4] = {0.f, 0.f, 0.f, 0.f};
            float d[4] = {0.f, 0.f, 0.f, 0.f};
            mma16816(c, a0, a1, a2, a3, Bf[q][0][0][0], Bf[q][0][0][1]);
            mma16816(c, a4, a5, a6, a7, Bf[q][0][1][0], Bf[q][0][1][1]);
            mma16816(d, a0, a1, a2, a3, Bf[q][1][0][0], Bf[q][1][0][1]);
            mma16816(d, a4, a5, a6, a7, Bf[q][1][1][0], Bf[q][1][1][1]);
            u64 p0 = ((u64)h2pack(d[0], d[1]) << 32) | h2pack(c[0], c[1]);
            u64 p1 = ((u64)h2pack(d[2], d[3]) << 32) | h2pack(c[2], c[3]);
            size_t op = q * 4 + tg;
            g_T2[(size_t)(nb + gr)     * 256 + w * 16 + op] = p0;
            g_T2[(size_t)(nb + gr + 8) * 256 + w * 16 + op] = p1;
        }
        if (w < 8) {
            float c[4] = {0.f, 0.f, 0.f, 0.f};
            mma16816(c, a0, a1, a2, a3, Bs[0][0], Bs[0][1]);
            mma16816(c, a4, a5, a6, a7, Bs[1][0], Bs[1][1]);
            if (w < 4) {
                int o = w * 8 + 2 * tg;
                *(float2*)(g_xb + (nb + gr)     * 32 + o) = make_float2(c[0], c[1]);
                *(float2*)(g_xb + (nb + gr + 8) * 32 + o) = make_float2(c[2], c[3]);
            } else {
                int o = (w - 4) * 8 + 2 * tg;
                *(float2*)(g_xr + (nb + gr)     * 32 + o) =
                    make_float2(c[0] + biasv.x, c[1] + biasv.y);
                *(float2*)(g_xr + (nb + gr + 8) * 32 + o) =
                    make_float2(c[2] + biasv.x, c[3] + biasv.y);
            }
        }
    }
}

// ---- edge kernel: 4 edges per warp (8-lane quads), lane = o-quad; LDG.128 T, red.v4 ----
__global__ void k_edge(const float* __restrict__ ea, const int* __restrict__ ei,
                       const float* __restrict__ w1, const float* __restrict__ b1) {
    int wrp = (blockIdx.x * blockDim.x + threadIdx.x) >> 5;
    if (wrp >= Ee / 4) return;
    int lane = threadIdx.x & 31;
    int grp = lane >> 3;
    int q = lane & 7;
    int e = 4 * wrp + grp;
    int src = __ldg(&ei[e]);
    int dst = __ldg(&ei[Ee + e]);
    float4 a = __ldg((const float4*)ea + e);

    float4 bv  = __ldg((const float4*)(b1 + 4 * q));
    float4 w0v = __ldg((const float4*)(w1 + 0 * 32 + 4 * q));
    float4 w1v = __ldg((const float4*)(w1 + 1 * 32 + 4 * q));
    float4 w2v = __ldg((const float4*)(w1 + 2 * 32 + 4 * q));
    float4 w3v = __ldg((const float4*)(w1 + 3 * 32 + 4 * q));
    float h0 = fmaxf(bv.x + a.x * w0v.x + a.y * w1v.x + a.z * w2v.x + a.w * w3v.x, 0.f);
    float h1 = fmaxf(bv.y + a.x * w0v.y + a.y * w1v.y + a.z * w2v.y + a.w * w3v.y, 0.f);
    float h2v = fmaxf(bv.z + a.x * w0v.z + a.y * w1v.z + a.z * w2v.z + a.w * w3v.z, 0.f);
    float h3 = fmaxf(bv.w + a.x * w0v.w + a.y * w1v.w + a.z * w2v.w + a.w * w3v.w, 0.f);

    float4 xbv = __ldg((const float4*)(g_xb + src * 32 + 4 * q));
    const uint4* Tp = (const uint4*)(g_T2 + (size_t)src * 256) + q;

    float sA0 = 0.f, sA1 = 0.f, sA2 = 0.f, sA3 = 0.f;
    float sB0 = 0.f, sB1 = 0.f, sB2 = 0.f, sB3 = 0.f;
    int base = lane & 24;
#pragma unroll
    for (int kp = 0; kp < 16; kp++) {
        int sl = base + (kp >> 1);
        float hA, hB;
        if ((kp & 1) == 0) {
            hA = __shfl_sync(0xffffffffu, h0, sl);
            hB = __shfl_sync(0xffffffffu, h1, sl);
        } else {
            hA = __shfl_sync(0xffffffffu, h2v, sl);
            hB = __shfl_sync(0xffffffffu, h3, sl);
        }
        uint4 t = __ldg(&Tp[kp * 8]);
        float2 f0 = __half22float2(*(__half2*)&t.x);
        float2 f1 = __half22float2(*(__half2*)&t.y);
        float2 f2 = __half22float2(*(__half2*)&t.z);
        float2 f3 = __half22float2(*(__half2*)&t.w);
        sA0 += hA * f0.x;  sA1 += hA * f0.y;  sA2 += hA * f2.x;  sA3 += hA * f2.y;
        sB0 += hB * f1.x;  sB1 += hB * f1.y;  sB2 += hB * f3.x;  sB3 += hB * f3.y;
    }
    red_add_v4(&g_agg[dst * 32 + 4 * q],
               xbv.x + sA0 + sB0, xbv.y + sA1 + sB1,
               xbv.z + sA2 + sB2, xbv.w + sA3 + sB3);
}

// ---- node L1: elementwise agg/deg + xr -> BN -> ReLU; resets agg ----
__global__ void k_node1(const float* __restrict__ bg, const float* __restrict__ bb,
                        const float* __restrict__ bm, const float* __restrict__ bv,
                        float* __restrict__ out) {
    int t = blockIdx.x * blockDim.x + threadIdx.x;
    if (t >= Nn * 8) return;
    int n = t >> 3, q = t & 7;
    float4 ag = *(const float4*)(g_agg + n * 32 + 4 * q);
    float4 xr = *(const float4*)(g_xr + n * 32 + 4 * q);
    float inv = 1.f / fmaxf(g_deg[n], 1.f);
    *(float4*)(g_agg + n * 32 + 4 * q) = make_float4(0.f, 0.f, 0.f, 0.f);
    float4 g = __ldg((const float4*)(bg + 4 * q));
    float4 b = __ldg((const float4*)(bb + 4 * q));
    float4 m = __ldg((const float4*)(bm + 4 * q));
    float4 v = __ldg((const float4*)(bv + 4 * q));
    float4 r;
    r.x = fmaxf((ag.x * inv + xr.x - m.x) * rsqrtf(v.x + BN_EPS) * g.x + b.x, 0.f);
    r.y = fmaxf((ag.y * inv + xr.y - m.y) * rsqrtf(v.y + BN_EPS) * g.y + b.y, 0.f);
    r.z = fmaxf((ag.z * inv + xr.z - m.z) * rsqrtf(v.z + BN_EPS) * g.z + b.z, 0.f);
    r.w = fmaxf((ag.w * inv + xr.w - m.w) * rsqrtf(v.w + BN_EPS) * g.w + b.w, 0.f);
    *(float4*)(out + n * 32 + 4 * q) = r;
}

// ---- node L2 + fused mean-pool scatter; resets agg & deg ----
__global__ void k_node2(const float* __restrict__ bg, const float* __restrict__ bb,
                        const float* __restrict__ bm, const float* __restrict__ bv,
                        const int* __restrict__ batch) {
    int t = blockIdx.x * blockDim.x + threadIdx.x;
    if (t >= Nn * 8) return;
    int n = t >> 3, q = t & 7;
    float4 ag = *(const float4*)(g_agg + n * 32 + 4 * q);
    float4 xr = *(const float4*)(g_xr + n * 32 + 4 * q);
    float inv = 1.f / fmaxf(g_deg[n], 1.f);
    *(float4*)(g_agg + n * 32 + 4 * q) = make_float4(0.f, 0.f, 0.f, 0.f);
    __syncwarp();
    if (q == 0) g_deg[n] = 0.f;
    float4 g = __ldg((const float4*)(bg + 4 * q));
    float4 b = __ldg((const float4*)(bb + 4 * q));
    float4 m = __ldg((const float4*)(bm + 4 * q));
    float4 v = __ldg((const float4*)(bv + 4 * q));
    float rx = fmaxf((ag.x * inv + xr.x - m.x) * rsqrtf(v.x + BN_EPS) * g.x + b.x, 0.f);
    float ry = fmaxf((ag.y * inv + xr.y - m.y) * rsqrtf(v.y + BN_EPS) * g.y + b.y, 0.f);
    float rz = fmaxf((ag.z * inv + xr.z - m.z) * rsqrtf(v.z + BN_EPS) * g.z + b.z, 0.f);
    float rw = fmaxf((ag.w * inv + xr.w - m.w) * rsqrtf(v.w + BN_EPS) * g.w + b.w, 0.f);
    int gph = __ldg(&batch[n]);
    red_add_v4(&g_pool[gph * 32 + 4 * q], rx, ry, rz, rw);
    if (q == 0) atomicAdd(&g_pcnt[gph], 1.f);
}

// ---- readout MLP; resets pool/pcnt ----
__global__ void k_readout(const float* __restrict__ r1w, const float* __restrict__ r1b,
                          const float* __restrict__ r2w, const float* __restrict__ r2b,
                          float* __restrict__ out) {
    int gph = blockIdx.x * blockDim.x + threadIdx.x;
    if (gph >= Gg) return;
    float c = fmaxf(g_pcnt[gph], 1.f);
    float p[Cc];
#pragma unroll
    for (int o = 0; o < Cc; o++) p[o] = g_pool[gph * Cc + o] / c;
    float res = r2b[0];
#pragma unroll
    for (int j = 0; j < 16; j++) {
        float hid = r1b[j];
#pragma unroll
        for (int o = 0; o < Cc; o++) hid += p[o] * r1w[o * 16 + j];
        res += fmaxf(hid, 0.f) * r2w[j];
    }
    out[gph] = res;
#pragma unroll
    for (int o = 0; o < Cc; o++) g_pool[gph * Cc + o] = 0.f;
    g_pcnt[gph] = 0.f;
}

extern "C" void kernel_launch(void* const* d_in, const int* in_sizes, int n_in,
                              void* d_out, int out_size) {
    const float* x     = (const float*)d_in[0];
    const float* ea    = (const float*)d_in[1];
    const float* e1w1  = (const float*)d_in[2];
    const float* e1b1  = (const float*)d_in[3];
    const float* e1w2  = (const float*)d_in[4];
    const float* e1b2  = (const float*)d_in[5];
    const float* root1 = (const float*)d_in[6];
    const float* bias1 = (const float*)d_in[7];
    const float* e2w1  = (const float*)d_in[8];
    const float* e2b1  = (const float*)d_in[9];
    const float* e2w2  = (const float*)d_in[10];
    const float* e2b2  = (const float*)d_in[11];
    const float* root2 = (const float*)d_in[12];
    const float* bias2 = (const float*)d_in[13];
    const float* bn1g  = (const float*)d_in[14];
    const float* bn1b  = (const float*)d_in[15];
    const float* bn1m  = (const float*)d_in[16];
    const float* bn1v  = (const float*)d_in[17];
    const float* bn2g  = (const float*)d_in[18];
    const float* bn2b  = (const float*)d_in[19];
    const float* bn2m  = (const float*)d_in[20];
    const float* bn2v  = (const float*)d_in[21];
    const float* r1w   = (const float*)d_in[22];
    const float* r1b   = (const float*)d_in[23];
    const float* r2w   = (const float*)d_in[24];
    const float* r2b   = (const float*)d_in[25];
    const int*   eidx  = (const int*)d_in[26];
    const int*   batch = (const int*)d_in[27];
    float* out = (float*)d_out;

    float* p_h1 = nullptr;
    cudaGetSymbolAddress((void**)&p_h1, g_h1);

    const int THR = 256;
    const int gEW = (Ee / 4 * 32 + THR - 1) / THR;    // 4 edges/warp: 3125 blocks
    const int gN8 = (Nn * 8 + THR - 1) / THR;         // 313 blocks

    // layer 1 (k_T computes T, xb, xr and the in-degree histogram)
    k_T<<<148, 512>>>(x, e1w2, e1b2, root1, bias1, eidx);
    k_edge<<<gEW, THR>>>(ea, eidx, e1w1, e1b1);
    k_node1<<<gN8, THR>>>(bn1g, bn1b, bn1m, bn1v, p_h1);

    // layer 2
    k_T<<<148, 512>>>(p_h1, e2w2, e2b2, root2, bias2, nullptr);
    k_edge<<<gEW, THR>>>(ea, eidx, e2w1, e2b1);
    k_node2<<<gN8, THR>>>(bn2g, bn2b, bn2m, bn2v, batch);

    // readout
    k_readout<<<1, 64>>>(r1w, r1b, r2w, r2b, out);
}

// round 11
// speedup vs baseline: 2.1757x; 1.0008x over previous
#include <cuda_runtime.h>
#include <cuda_fp16.h>

#define Nn 10000
#define Ee 100000
#define Cc 32
#define Gg 64
#define BN_EPS 1e-5f

typedef unsigned long long u64;
typedef unsigned int u32;

// ---- scratch (static device globals; zero-initialized at load) ----
// T2[n][kp][op] u64 = {h2(T[2kp][2op],T[2kp][2op+1]), h2(T[2kp+1][2op],T[2kp+1][2op+1])}
__device__ __align__(16) u64   g_T2[(size_t)Nn * 256];   // 20.48 MB
__device__ __align__(16) float g_xb[Nn * Cc];            // x @ b2
__device__ __align__(16) float g_xr[Nn * Cc];            // x @ root + bias
__device__ __align__(16) float g_agg[Nn * Cc];
__device__ float g_deg[Nn];
__device__ __align__(16) float g_pool[Gg * Cc];
__device__ float g_pcnt[Gg];

__device__ __forceinline__ void red_add_v4(float* addr, float a, float b, float c, float d) {
    asm volatile("red.global.add.v4.f32 [%0], {%1, %2, %3, %4};"
                 :: "l"(addr), "f"(a), "f"(b), "f"(c), "f"(d) : "memory");
}
__device__ __forceinline__ u32 h2pack(float lo, float hi) {
    __half2 h = __floats2half2_rn(lo, hi);
    return *(u32*)&h;
}
__device__ __forceinline__ void mma16816(float c[4], u32 a0, u32 a1, u32 a2, u32 a3,
                                         u32 b0, u32 b1) {
    asm("mma.sync.aligned.m16n8k16.row.col.f32.f16.f16.f32 "
        "{%0,%1,%2,%3}, {%4,%5,%6,%7}, {%8,%9}, {%0,%1,%2,%3};"
        : "+f"(c[0]), "+f"(c[1]), "+f"(c[2]), "+f"(c[3])
        : "r"(a0), "r"(a1), "r"(a2), "r"(a3), "r"(b0), "r"(b1));
}

// ---- k_T: T = x@w2 (HMMA) + xb = x@b2 (warps 0-3) + xr = x@root + bias (warps 4-7).
// Layer 1 (bg==null): input = xin, fused in-degree histogram (ei != null).
// Layer 2 (bg!=null): input tile computed on the fly = BN1(agg/deg + xr) ReLU; resets agg.
// Results staged in smem (xor-swizzled) then copied to g_T2 with coalesced stores.
__global__ void __launch_bounds__(512, 1)
k_T(const float* __restrict__ xin, const float* __restrict__ w2,
    const float* __restrict__ b2, const float* __restrict__ root,
    const float* __restrict__ bias, const int* __restrict__ ei,
    const float* __restrict__ bg, const float* __restrict__ bb,
    const float* __restrict__ bm, const float* __restrict__ bv) {
    int tid = threadIdx.x;
    int lane = tid & 31;
    int w = tid >> 5;                  // = kp
    int tg = lane & 3;
    int gr = lane >> 2;
    bool l2 = (bg != nullptr);

    if (ei) {   // fused in-degree (layer 1 only)
        for (int e = blockIdx.x * 512 + tid; e < Ee; e += gridDim.x * 512)
            atomicAdd(&g_deg[__ldg(&ei[Ee + e])], 1.f);
    }

    // ---- B fragments for w2 ----
    u32 Bf[4][2][2][2];
#pragma unroll
    for (int q = 0; q < 4; q++)
#pragma unroll
        for (int kk = 0; kk < 2; kk++) {
            const float* rb = w2 + (2 * w + kk) * 1024 + q * 8 + gr;
#pragma unroll
            for (int st = 0; st < 2; st++) {
                int i0 = 2 * tg + 16 * st;
                Bf[q][kk][st][0] = h2pack(__ldg(&rb[i0 * 32]),       __ldg(&rb[(i0 + 1) * 32]));
                Bf[q][kk][st][1] = h2pack(__ldg(&rb[(i0 + 8) * 32]), __ldg(&rb[(i0 + 9) * 32]));
            }
        }
    // side matrices: warps 0-3 -> b2 (octet w), warps 4-7 -> root (octet w-4)
    u32 Bs[2][2];
    float2 biasv = make_float2(0.f, 0.f);
    if (w < 8) {
        const float* src = (w < 4) ? (b2 + w * 8 + gr) : (root + (w - 4) * 8 + gr);
#pragma unroll
        for (int st = 0; st < 2; st++) {
            int i0 = 2 * tg + 16 * st;
            Bs[st][0] = h2pack(__ldg(&src[i0 * 32]),       __ldg(&src[(i0 + 1) * 32]));
            Bs[st][1] = h2pack(__ldg(&src[(i0 + 8) * 32]), __ldg(&src[(i0 + 9) * 32]));
        }
        if (w >= 4) biasv = __ldg((const float2*)(bias + (w - 4) * 8 + 2 * tg));
    }

    // hoisted BN constants for layer-2 input transform (channel fixed per thread)
    float scale = 0.f, shift = 0.f;
    if (l2) {
        int i = tid & 31;
        float s = rsqrtf(__ldg(&bv[i]) + BN_EPS) * __ldg(&bg[i]);
        scale = s;
        shift = __ldg(&bb[i]) - __ldg(&bm[i]) * s;
    }

    __shared__ __half xs[16 * 40];
    __shared__ u64 ts[16 * 256];       // 32KB staging for T2 tile

    // prefetch first tile input
    int tile = blockIdx.x;
    float pA = 0.f, pX = 0.f;
    if (tile < 625) {
        if (l2) { pA = g_agg[tile * 512 + tid]; pX = g_xr[tile * 512 + tid]; }
        else      pA = __ldg(&xin[tile * 512 + tid]);
    }

    for (; tile < 625; tile += gridDim.x) {
        int nb = tile * 16;
        int j = tid >> 5, i = tid & 31;
        float xv;
        if (l2) {
            float dg = fmaxf(g_deg[nb + j], 1.f);
            xv = fmaxf((pA / dg + pX) * scale + shift, 0.f);   // h1 computed on the fly
            g_agg[tile * 512 + tid] = 0.f;                     // reset for layer 2 edges
        } else xv = pA;
        xs[j * 40 + i] = __float2half(xv);
        __syncthreads();

        const u32* xp = (const u32*)xs;
        int ab = gr * 20 + tg;
        u32 a0 = xp[ab],       a1 = xp[ab + 160];
        u32 a2 = xp[ab + 4],   a3 = xp[ab + 164];
        u32 a4 = xp[ab + 8],   a5 = xp[ab + 168];
        u32 a6 = xp[ab + 12],  a7 = xp[ab + 172];

        // prefetch next tile (hidden under MMAs)
        int tn = tile + gridDim.x;
        if (tn < 625) {
            if (l2) { pA = g_agg[tn * 512 + tid]; pX = g_xr[tn * 512 + tid]; }
            else      pA = __ldg(&xin[tn * 512 + tid]);
        }

        int x4 = (gr & 3) * 4;         // xor swizzle keys (gr+8 has same low bits)
#pragma unroll
        for (int q = 0; q < 4; q++) {
            float c[4] = {0.f, 0.f, 0.f, 0.f};
            float d[4] = {0.f, 0.f, 0.f, 0.f};
            mma16816(c, a0, a1, a2, a3, Bf[q][0][0][0], Bf[q][0][0][1]);
            mma16816(c, a4, a5, a6, a7, Bf[q][0][1][0], Bf[q][0][1][1]);
            mma16816(d, a0, a1, a2, a3, Bf[q][1][0][0], Bf[q][1][0][1]);
            mma16816(d, a4, a5, a6, a7, Bf[q][1][1][0], Bf[q][1][1][1]);
            u64 p0 = ((u64)h2pack(d[0], d[1]) << 32) | h2pack(c[0], c[1]);
            u64 p1 = ((u64)h2pack(d[2], d[3]) << 32) | h2pack(c[2], c[3]);
            int c0 = w * 16 + q * 4 + tg;
            ts[gr * 256       + (c0 ^ x4)] = p0;
            ts[(gr + 8) * 256 + (c0 ^ x4)] = p1;
        }
        if (w < 8) {
            float c[4] = {0.f, 0.f, 0.f, 0.f};
            mma16816(c, a0, a1, a2, a3, Bs[0][0], Bs[0][1]);
            mma16816(c, a4, a5, a6, a7, Bs[1][0], Bs[1][1]);
            if (w < 4) {
                int o = w * 8 + 2 * tg;
                *(float2*)(g_xb + (nb + gr)     * 32 + o) = make_float2(c[0], c[1]);
                *(float2*)(g_xb + (nb + gr + 8) * 32 + o) = make_float2(c[2], c[3]);
            } else {
                int o = (w - 4) * 8 + 2 * tg;
                *(float2*)(g_xr + (nb + gr)     * 32 + o) =
                    make_float2(c[0] + biasv.x, c[1] + biasv.y);
                *(float2*)(g_xr + (nb + gr + 8) * 32 + o) =
                    make_float2(c[2] + biasv.x, c[3] + biasv.y);
            }
        }
        __syncthreads();

        // coalesced copy staging -> g_T2 (un-swizzle on the LDS side)
        u64* dst = g_T2 + (size_t)nb * 256;
#pragma unroll
        for (int r = 0; r < 8; r++) {
            int i64 = r * 512 + tid;
            int row = i64 >> 8, cc = i64 & 255;
            dst[i64] = ts[row * 256 + (cc ^ ((row & 3) * 4))];
        }
        __syncthreads();
    }
}

// ---- edge kernel: 4 edges per warp (8-lane quads), lane = o-quad; LDG.128 T, red.v4 ----
__global__ void k_edge(const float* __restrict__ ea, const int* __restrict__ ei,
                       const float* __restrict__ w1, const float* __restrict__ b1) {
    int wrp = (blockIdx.x * blockDim.x + threadIdx.x) >> 5;
    if (wrp >= Ee / 4) return;
    int lane = threadIdx.x & 31;
    int grp = lane >> 3;
    int q = lane & 7;
    int e = 4 * wrp + grp;
    int src = __ldg(&ei[e]);
    int dst = __ldg(&ei[Ee + e]);
    float4 a = __ldg((const float4*)ea + e);

    float4 bv  = __ldg((const float4*)(b1 + 4 * q));
    float4 w0v = __ldg((const float4*)(w1 + 0 * 32 + 4 * q));
    float4 w1v = __ldg((const float4*)(w1 + 1 * 32 + 4 * q));
    float4 w2v = __ldg((const float4*)(w1 + 2 * 32 + 4 * q));
    float4 w3v = __ldg((const float4*)(w1 + 3 * 32 + 4 * q));
    float h0 = fmaxf(bv.x + a.x * w0v.x + a.y * w1v.x + a.z * w2v.x + a.w * w3v.x, 0.f);
    float h1 = fmaxf(bv.y + a.x * w0v.y + a.y * w1v.y + a.z * w2v.y + a.w * w3v.y, 0.f);
    float h2v = fmaxf(bv.z + a.x * w0v.z + a.y * w1v.z + a.z * w2v.z + a.w * w3v.z, 0.f);
    float h3 = fmaxf(bv.w + a.x * w0v.w + a.y * w1v.w + a.z * w2v.w + a.w * w3v.w, 0.f);

    float4 xbv = __ldg((const float4*)(g_xb + src * 32 + 4 * q));
    const uint4* Tp = (const uint4*)(g_T2 + (size_t)src * 256) + q;

    float sA0 = 0.f, sA1 = 0.f, sA2 = 0.f, sA3 = 0.f;
    float sB0 = 0.f, sB1 = 0.f, sB2 = 0.f, sB3 = 0.f;
    int base = lane & 24;
#pragma unroll
    for (int kp = 0; kp < 16; kp++) {
        int sl = base + (kp >> 1);
        float hA, hB;
        if ((kp & 1) == 0) {
            hA = __shfl_sync(0xffffffffu, h0, sl);
            hB = __shfl_sync(0xffffffffu, h1, sl);
        } else {
            hA = __shfl_sync(0xffffffffu, h2v, sl);
            hB = __shfl_sync(0xffffffffu, h3, sl);
        }
        uint4 t = __ldg(&Tp[kp * 8]);
        float2 f0 = __half22float2(*(__half2*)&t.x);
        float2 f1 = __half22float2(*(__half2*)&t.y);
        float2 f2 = __half22float2(*(__half2*)&t.z);
        float2 f3 = __half22float2(*(__half2*)&t.w);
        sA0 += hA * f0.x;  sA1 += hA * f0.y;  sA2 += hA * f2.x;  sA3 += hA * f2.y;
        sB0 += hB * f1.x;  sB1 += hB * f1.y;  sB2 += hB * f3.x;  sB3 += hB * f3.y;
    }
    red_add_v4(&g_agg[dst * 32 + 4 * q],
               xbv.x + sA0 + sB0, xbv.y + sA1 + sB1,
               xbv.z + sA2 + sB2, xbv.w + sA3 + sB3);
}

// ---- node L2 + fused mean-pool scatter; resets agg & deg ----
__global__ void k_node2(const float* __restrict__ bg, const float* __restrict__ bb,
                        const float* __restrict__ bm, const float* __restrict__ bv,
                        const int* __restrict__ batch) {
    int t = blockIdx.x * blockDim.x + threadIdx.x;
    if (t >= Nn * 8) return;
    int n = t >> 3, q = t & 7;
    float4 ag = *(const float4*)(g_agg + n * 32 + 4 * q);
    float4 xr = *(const float4*)(g_xr + n * 32 + 4 * q);
    float inv = 1.f / fmaxf(g_deg[n], 1.f);
    *(float4*)(g_agg + n * 32 + 4 * q) = make_float4(0.f, 0.f, 0.f, 0.f);
    __syncwarp();
    if (q == 0) g_deg[n] = 0.f;
    float4 g = __ldg((const float4*)(bg + 4 * q));
    float4 b = __ldg((const float4*)(bb + 4 * q));
    float4 m = __ldg((const float4*)(bm + 4 * q));
    float4 v = __ldg((const float4*)(bv + 4 * q));
    float rx = fmaxf((ag.x * inv + xr.x - m.x) * rsqrtf(v.x + BN_EPS) * g.x + b.x, 0.f);
    float ry = fmaxf((ag.y * inv + xr.y - m.y) * rsqrtf(v.y + BN_EPS) * g.y + b.y, 0.f);
    float rz = fmaxf((ag.z * inv + xr.z - m.z) * rsqrtf(v.z + BN_EPS) * g.z + b.z, 0.f);
    float rw = fmaxf((ag.w * inv + xr.w - m.w) * rsqrtf(v.w + BN_EPS) * g.w + b.w, 0.f);
    int gph = __ldg(&batch[n]);
    red_add_v4(&g_pool[gph * 32 + 4 * q], rx, ry, rz, rw);
    if (q == 0) atomicAdd(&g_pcnt[gph], 1.f);
}

// ---- readout MLP; resets pool/pcnt ----
__global__ void k_readout(const float* __restrict__ r1w, const float* __restrict__ r1b,
                          const float* __restrict__ r2w, const float* __restrict__ r2b,
                          float* __restrict__ out) {
    int gph = blockIdx.x * blockDim.x + threadIdx.x;
    if (gph >= Gg) return;
    float c = fmaxf(g_pcnt[gph], 1.f);
    float p[Cc];
#pragma unroll
    for (int o = 0; o < Cc; o++) p[o] = g_pool[gph * Cc + o] / c;
    float res = r2b[0];
#pragma unroll
    for (int j = 0; j < 16; j++) {
        float hid = r1b[j];
#pragma unroll
        for (int o = 0; o < Cc; o++) hid += p[o] * r1w[o * 16 + j];
        res += fmaxf(hid, 0.f) * r2w[j];
    }
    out[gph] = res;
#pragma unroll
    for (int o = 0; o < Cc; o++) g_pool[gph * Cc + o] = 0.f;
    g_pcnt[gph] = 0.f;
}

extern "C" void kernel_launch(void* const* d_in, const int* in_sizes, int n_in,
                              void* d_out, int out_size) {
    const float* x     = (const float*)d_in[0];
    const float* ea    = (const float*)d_in[1];
    const float* e1w1  = (const float*)d_in[2];
    const float* e1b1  = (const float*)d_in[3];
    const float* e1w2  = (const float*)d_in[4];
    const float* e1b2  = (const float*)d_in[5];
    const float* root1 = (const float*)d_in[6];
    const float* bias1 = (const float*)d_in[7];
    const float* e2w1  = (const float*)d_in[8];
    const float* e2b1  = (const float*)d_in[9];
    const float* e2w2  = (const float*)d_in[10];
    const float* e2b2  = (const float*)d_in[11];
    const float* root2 = (const float*)d_in[12];
    const float* bias2 = (const float*)d_in[13];
    const float* bn1g  = (const float*)d_in[14];
    const float* bn1b  = (const float*)d_in[15];
    const float* bn1m  = (const float*)d_in[16];
    const float* bn1v  = (const float*)d_in[17];
    const float* bn2g  = (const float*)d_in[18];
    const float* bn2b  = (const float*)d_in[19];
    const float* bn2m  = (const float*)d_in[20];
    const float* bn2v  = (const float*)d_in[21];
    const float* r1w   = (const float*)d_in[22];
    const float* r1b   = (const float*)d_in[23];
    const float* r2w   = (const float*)d_in[24];
    const float* r2b   = (const float*)d_in[25];
    const int*   eidx  = (const int*)d_in[26];
    const int*   batch = (const int*)d_in[27];
    float* out = (float*)d_out;

    const int THR = 256;
    const int gEW = (Ee / 4 * 32 + THR - 1) / THR;    // 3125 blocks
    const int gN8 = (Nn * 8 + THR - 1) / THR;         // 313 blocks

    // layer 1: T/xb/xr from x, fused deg histogram
    k_T<<<148, 512>>>(x, e1w2, e1b2, root1, bias1, eidx,
                      nullptr, nullptr, nullptr, nullptr);
    k_edge<<<gEW, THR>>>(ea, eidx, e1w1, e1b1);

    // layer 2: k_T consumes agg/xr directly (node-1 epilogue fused into tile load)
    k_T<<<148, 512>>>(nullptr, e2w2, e2b2, root2, bias2, nullptr,
                      bn1g, bn1b, bn1m, bn1v);
    k_edge<<<gEW, THR>>>(ea, eidx, e2w1, e2b1);
    k_node2<<<gN8, THR>>>(bn2g, bn2b, bn2m, bn2v, batch);

    // readout
    k_readout<<<1, 64>>>(r1w, r1b, r2w, r2b, out);
}

// round 12
// speedup vs baseline: 2.1904x; 1.0067x over previous
#include <cuda_runtime.h>
#include <cuda_fp16.h>

#define Nn 10000
#define Ee 100000
#define Cc 32
#define Gg 64
#define BN_EPS 1e-5f

typedef unsigned long long u64;
typedef unsigned int u32;

// ---- scratch (static device globals; zero-initialized at load) ----
// T2[n][kp][op] u64 = {h2(T[2kp][2op],T[2kp][2op+1]), h2(T[2kp+1][2op],T[2kp+1][2op+1])}
__device__ __align__(16) u64   g_T2[(size_t)Nn * 256];   // 20.48 MB
__device__ __align__(16) float g_xb[Nn * Cc];            // x @ b2
__device__ __align__(16) float g_xr[Nn * Cc];            // x @ root + bias
__device__ __align__(16) float g_agg[Nn * Cc];
__device__ float g_deg[Nn];
__device__ __align__(16) float g_pool[Gg * Cc];
__device__ float g_pcnt[Gg];
__device__ unsigned g_done;                              // last-block arrival counter

__device__ __forceinline__ void red_add_v4(float* addr, float a, float b, float c, float d) {
    asm volatile("red.global.add.v4.f32 [%0], {%1, %2, %3, %4};"
                 :: "l"(addr), "f"(a), "f"(b), "f"(c), "f"(d) : "memory");
}
__device__ __forceinline__ u32 h2pack(float lo, float hi) {
    __half2 h = __floats2half2_rn(lo, hi);
    return *(u32*)&h;
}
__device__ __forceinline__ void mma16816(float c[4], u32 a0, u32 a1, u32 a2, u32 a3,
                                         u32 b0, u32 b1) {
    asm("mma.sync.aligned.m16n8k16.row.col.f32.f16.f16.f32 "
        "{%0,%1,%2,%3}, {%4,%5,%6,%7}, {%8,%9}, {%0,%1,%2,%3};"
        : "+f"(c[0]), "+f"(c[1]), "+f"(c[2]), "+f"(c[3])
        : "r"(a0), "r"(a1), "r"(a2), "r"(a3), "r"(b0), "r"(b1));
}

// ---- k_T: T = x@w2 (HMMA) + xb = x@b2 (warps 0-3) + xr = x@root + bias (warps 4-7).
// Layer 1 (bg==null): input = xin, fused in-degree histogram (ei != null).
// Layer 2 (bg!=null): input tile computed on the fly = BN1(agg/deg + xr) ReLU; resets agg.
__global__ void __launch_bounds__(512, 1)
k_T(const float* __restrict__ xin, const float* __restrict__ w2,
    const float* __restrict__ b2, const float* __restrict__ root,
    const float* __restrict__ bias, const int* __restrict__ ei,
    const float* __restrict__ bg, const float* __restrict__ bb,
    const float* __restrict__ bm, const float* __restrict__ bv) {
    int tid = threadIdx.x;
    int lane = tid & 31;
    int w = tid >> 5;                  // = kp
    int tg = lane & 3;
    int gr = lane >> 2;
    bool l2 = (bg != nullptr);

    if (ei) {   // fused in-degree (layer 1 only)
        for (int e = blockIdx.x * 512 + tid; e < Ee; e += gridDim.x * 512)
            atomicAdd(&g_deg[__ldg(&ei[Ee + e])], 1.f);
    }

    u32 Bf[4][2][2][2];
#pragma unroll
    for (int q = 0; q < 4; q++)
#pragma unroll
        for (int kk = 0; kk < 2; kk++) {
            const float* rb = w2 + (2 * w + kk) * 1024 + q * 8 + gr;
#pragma unroll
            for (int st = 0; st < 2; st++) {
                int i0 = 2 * tg + 16 * st;
                Bf[q][kk][st][0] = h2pack(__ldg(&rb[i0 * 32]),       __ldg(&rb[(i0 + 1) * 32]));
                Bf[q][kk][st][1] = h2pack(__ldg(&rb[(i0 + 8) * 32]), __ldg(&rb[(i0 + 9) * 32]));
            }
        }
    u32 Bs[2][2];
    float2 biasv = make_float2(0.f, 0.f);
    if (w < 8) {
        const float* src = (w < 4) ? (b2 + w * 8 + gr) : (root + (w - 4) * 8 + gr);
#pragma unroll
        for (int st = 0; st < 2; st++) {
            int i0 = 2 * tg + 16 * st;
            Bs[st][0] = h2pack(__ldg(&src[i0 * 32]),       __ldg(&src[(i0 + 1) * 32]));
            Bs[st][1] = h2pack(__ldg(&src[(i0 + 8) * 32]), __ldg(&src[(i0 + 9) * 32]));
        }
        if (w >= 4) biasv = __ldg((const float2*)(bias + (w - 4) * 8 + 2 * tg));
    }

    float scale = 0.f, shift = 0.f;
    if (l2) {
        int i = tid & 31;
        float s = rsqrtf(__ldg(&bv[i]) + BN_EPS) * __ldg(&bg[i]);
        scale = s;
        shift = __ldg(&bb[i]) - __ldg(&bm[i]) * s;
    }

    __shared__ __half xs[16 * 40];
    __shared__ u64 ts[16 * 256];

    int tile = blockIdx.x;
    float pA = 0.f, pX = 0.f;
    if (tile < 625) {
        if (l2) { pA = g_agg[tile * 512 + tid]; pX = g_xr[tile * 512 + tid]; }
        else      pA = __ldg(&xin[tile * 512 + tid]);
    }

    for (; tile < 625; tile += gridDim.x) {
        int nb = tile * 16;
        int j = tid >> 5, i = tid & 31;
        float xv;
        if (l2) {
            float dg = fmaxf(g_deg[nb + j], 1.f);
            xv = fmaxf((pA / dg + pX) * scale + shift, 0.f);
            g_agg[tile * 512 + tid] = 0.f;
        } else xv = pA;
        xs[j * 40 + i] = __float2half(xv);
        __syncthreads();

        const u32* xp = (const u32*)xs;
        int ab = gr * 20 + tg;
        u32 a0 = xp[ab],       a1 = xp[ab + 160];
        u32 a2 = xp[ab + 4],   a3 = xp[ab + 164];
        u32 a4 = xp[ab + 8],   a5 = xp[ab + 168];
        u32 a6 = xp[ab + 12],  a7 = xp[ab + 172];

        int tn = tile + gridDim.x;
        if (tn < 625) {
            if (l2) { pA = g_agg[tn * 512 + tid]; pX = g_xr[tn * 512 + tid]; }
            else      pA = __ldg(&xin[tn * 512 + tid]);
        }

        int x4 = (gr & 3) * 4;
#pragma unroll
        for (int q = 0; q < 4; q++) {
            float c[4] = {0.f, 0.f, 0.f, 0.f};
            float d[4] = {0.f, 0.f, 0.f, 0.f};
            mma16816(c, a0, a1, a2, a3, Bf[q][0][0][0], Bf[q][0][0][1]);
            mma16816(c, a4, a5, a6, a7, Bf[q][0][1][0], Bf[q][0][1][1]);
            mma16816(d, a0, a1, a2, a3, Bf[q][1][0][0], Bf[q][1][0][1]);
            mma16816(d, a4, a5, a6, a7, Bf[q][1][1][0], Bf[q][1][1][1]);
            u64 p0 = ((u64)h2pack(d[0], d[1]) << 32) | h2pack(c[0], c[1]);
            u64 p1 = ((u64)h2pack(d[2], d[3]) << 32) | h2pack(c[2], c[3]);
            int c0 = w * 16 + q * 4 + tg;
            ts[gr * 256       + (c0 ^ x4)] = p0;
            ts[(gr + 8) * 256 + (c0 ^ x4)] = p1;
        }
        if (w < 8) {
            float c[4] = {0.f, 0.f, 0.f, 0.f};
            mma16816(c, a0, a1, a2, a3, Bs[0][0], Bs[0][1]);
            mma16816(c, a4, a5, a6, a7, Bs[1][0], Bs[1][1]);
            if (w < 4) {
                int o = w * 8 + 2 * tg;
                *(float2*)(g_xb + (nb + gr)     * 32 + o) = make_float2(c[0], c[1]);
                *(float2*)(g_xb + (nb + gr + 8) * 32 + o) = make_float2(c[2], c[3]);
            } else {
                int o = (w - 4) * 8 + 2 * tg;
                *(float2*)(g_xr + (nb + gr)     * 32 + o) =
                    make_float2(c[0] + biasv.x, c[1] + biasv.y);
                *(float2*)(g_xr + (nb + gr + 8) * 32 + o) =
                    make_float2(c[2] + biasv.x, c[3] + biasv.y);
            }
        }
        __syncthreads();

        u64* dst = g_T2 + (size_t)nb * 256;
#pragma unroll
        for (int r = 0; r < 8; r++) {
            int i64 = r * 512 + tid;
            int row = i64 >> 8, cc = i64 & 255;
            dst[i64] = ts[row * 256 + (cc ^ ((row & 3) * 4))];
        }
        __syncthreads();
    }
}

// ---- edge kernel: 4 edges/warp, lane = o-quad; HFMA2 core, fp32 flush every 8 k-pairs ----
__global__ void __launch_bounds__(256)
k_edge(const float* __restrict__ ea, const int* __restrict__ ei,
       const float* __restrict__ w1, const float* __restrict__ b1) {
    int wrp = (blockIdx.x * blockDim.x + threadIdx.x) >> 5;
    if (wrp >= Ee / 4) return;
    int lane = threadIdx.x & 31;
    int grp = lane >> 3;
    int q = lane & 7;
    int e = 4 * wrp + grp;
    int src = __ldg(&ei[e]);
    int dst = __ldg(&ei[Ee + e]);
    float4 a = __ldg((const float4*)ea + e);

    float4 bv  = __ldg((const float4*)(b1 + 4 * q));
    float4 w0v = __ldg((const float4*)(w1 + 0 * 32 + 4 * q));
    float4 w1v = __ldg((const float4*)(w1 + 1 * 32 + 4 * q));
    float4 w2v = __ldg((const float4*)(w1 + 2 * 32 + 4 * q));
    float4 w3v = __ldg((const float4*)(w1 + 3 * 32 + 4 * q));
    float h0 = fmaxf(bv.x + a.x * w0v.x + a.y * w1v.x + a.z * w2v.x + a.w * w3v.x, 0.f);
    float h1 = fmaxf(bv.y + a.x * w0v.y + a.y * w1v.y + a.z * w2v.y + a.w * w3v.y, 0.f);
    float h2v = fmaxf(bv.z + a.x * w0v.z + a.y * w1v.z + a.z * w2v.z + a.w * w3v.z, 0.f);
    float h3 = fmaxf(bv.w + a.x * w0v.w + a.y * w1v.w + a.z * w2v.w + a.w * w3v.w, 0.f);
    u32 hlo = h2pack(h0, h1);          // h[4q], h[4q+1]
    u32 hhi = h2pack(h2v, h3);         // h[4q+2], h[4q+3]

    float4 xbv = __ldg((const float4*)(g_xb + src * 32 + 4 * q));
    const uint4* Tp = (const uint4*)(g_T2 + (size_t)src * 256) + q;

    float r0 = xbv.x, r1 = xbv.y, r2 = xbv.z, r3 = xbv.w;
    __half2 z = __floats2half2_rn(0.f, 0.f);
    __half2 aA01 = z, aB01 = z, aA23 = z, aB23 = z;
    int base = lane & 24;
#pragma unroll
    for (int kp = 0; kp < 16; kp++) {
        u32 hh = __shfl_sync(0xffffffffu, (kp & 1) ? hhi : hlo, base + (kp >> 1));
        __half2 hph = *(__half2*)&hh;           // (h[2kp], h[2kp+1])
        __half2 hA = __low2half2(hph);          // splat h[2kp]
        __half2 hB = __high2half2(hph);         // splat h[2kp+1]
        uint4 t = __ldg(&Tp[kp * 8]);
        aA01 = __hfma2(hA, *(__half2*)&t.x, aA01);
        aB01 = __hfma2(hB, *(__half2*)&t.y, aB01);
        aA23 = __hfma2(hA, *(__half2*)&t.z, aA23);
        aB23 = __hfma2(hB, *(__half2*)&t.w, aB23);
        if (kp == 7 || kp == 15) {              // flush to fp32 (chains <= 8 adds)
            float2 fA01 = __half22float2(aA01), fB01 = __half22float2(aB01);
            float2 fA23 = __half22float2(aA23), fB23 = __half22float2(aB23);
            r0 += fA01.x + fB01.x;  r1 += fA01.y + fB01.y;
            r2 += fA23.x + fB23.x;  r3 += fA23.y + fB23.y;
            aA01 = z; aB01 = z; aA23 = z; aB23 = z;
        }
    }
    red_add_v4(&g_agg[dst * 32 + 4 * q], r0, r1, r2, r3);
}

// ---- node L2 + mean-pool scatter + LAST-BLOCK fused readout; resets agg/deg/pool/pcnt ----
__global__ void __launch_bounds__(256)
k_node2(const float* __restrict__ bg, const float* __restrict__ bb,
        const float* __restrict__ bm, const float* __restrict__ bv,
        const int* __restrict__ batch,
        const float* __restrict__ r1w, const float* __restrict__ r1b,
        const float* __restrict__ r2w, const float* __restrict__ r2b,
        float* __restrict__ out) {
    int t = blockIdx.x * blockDim.x + threadIdx.x;
    if (t < Nn * 8) {
        int n = t >> 3, q = t & 7;
        float4 ag = *(const float4*)(g_agg + n * 32 + 4 * q);
        float4 xr = *(const float4*)(g_xr + n * 32 + 4 * q);
        float inv = 1.f / fmaxf(g_deg[n], 1.f);
        *(float4*)(g_agg + n * 32 + 4 * q) = make_float4(0.f, 0.f, 0.f, 0.f);
        __syncwarp();
        if (q == 0) g_deg[n] = 0.f;
        float4 g = __ldg((const float4*)(bg + 4 * q));
        float4 b = __ldg((const float4*)(bb + 4 * q));
        float4 m = __ldg((const float4*)(bm + 4 * q));
        float4 v = __ldg((const float4*)(bv + 4 * q));
        float rx = fmaxf((ag.x * inv + xr.x - m.x) * rsqrtf(v.x + BN_EPS) * g.x + b.x, 0.f);
        float ry = fmaxf((ag.y * inv + xr.y - m.y) * rsqrtf(v.y + BN_EPS) * g.y + b.y, 0.f);
        float rz = fmaxf((ag.z * inv + xr.z - m.z) * rsqrtf(v.z + BN_EPS) * g.z + b.z, 0.f);
        float rw = fmaxf((ag.w * inv + xr.w - m.w) * rsqrtf(v.w + BN_EPS) * g.w + b.w, 0.f);
        int gph = __ldg(&batch[n]);
        red_add_v4(&g_pool[gph * 32 + 4 * q], rx, ry, rz, rw);
        if (q == 0) atomicAdd(&g_pcnt[gph], 1.f);
    }

    // last-block fused readout
    __shared__ bool isLast;
    __threadfence();
    __syncthreads();
    if (threadIdx.x == 0)
        isLast = (atomicAdd(&g_done, 1u) == gridDim.x - 1);
    __syncthreads();
    if (isLast) {
        __threadfence();
        int gph = threadIdx.x;
        if (gph < Gg) {
            float c = fmaxf(g_pcnt[gph], 1.f);
            float p[Cc];
#pragma unroll
            for (int o = 0; o < Cc; o++) p[o] = g_pool[gph * Cc + o] / c;
            float res = r2b[0];
#pragma unroll
            for (int jj = 0; jj < 16; jj++) {
                float hid = r1b[jj];
#pragma unroll
                for (int o = 0; o < Cc; o++) hid += p[o] * r1w[o * 16 + jj];
                res += fmaxf(hid, 0.f) * r2w[jj];
            }
            out[gph] = res;
#pragma unroll
            for (int o = 0; o < Cc; o++) g_pool[gph * Cc + o] = 0.f;
            g_pcnt[gph] = 0.f;
        }
        if (threadIdx.x == 0) g_done = 0;
    }
}

extern "C" void kernel_launch(void* const* d_in, const int* in_sizes, int n_in,
                              void* d_out, int out_size) {
    const float* x     = (const float*)d_in[0];
    const float* ea    = (const float*)d_in[1];
    const float* e1w1  = (const float*)d_in[2];
    const float* e1b1  = (const float*)d_in[3];
    const float* e1w2  = (const float*)d_in[4];
    const float* e1b2  = (const float*)d_in[5];
    const float* root1 = (const float*)d_in[6];
    const float* bias1 = (const float*)d_in[7];
    const float* e2w1  = (const float*)d_in[8];
    const float* e2b1  = (const float*)d_in[9];
    const float* e2w2  = (const float*)d_in[10];
    const float* e2b2  = (const float*)d_in[11];
    const float* root2 = (const float*)d_in[12];
    const float* bias2 = (const float*)d_in[13];
    const float* bn1g  = (const float*)d_in[14];
    const float* bn1b  = (const float*)d_in[15];
    const float* bn1m  = (const float*)d_in[16];
    const float* bn1v  = (const float*)d_in[17];
    const float* bn2g  = (const float*)d_in[18];
    const float* bn2b  = (const float*)d_in[19];
    const float* bn2m  = (const float*)d_in[20];
    const float* bn2v  = (const float*)d_in[21];
    const float* r1w   = (const float*)d_in[22];
    const float* r1b   = (const float*)d_in[23];
    const float* r2w   = (const float*)d_in[24];
    const float* r2b   = (const float*)d_in[25];
    const int*   eidx  = (const int*)d_in[26];
    const int*   batch = (const int*)d_in[27];
    float* out = (float*)d_out;

    const int THR = 256;
    const int gEW = (Ee / 4 * 32 + THR - 1) / THR;    // 3125 blocks
    const int gN8 = (Nn * 8 + THR - 1) / THR;         // 313 blocks

    // layer 1
    k_T<<<148, 512>>>(x, e1w2, e1b2, root1, bias1, eidx,
                      nullptr, nullptr, nullptr, nullptr);
    k_edge<<<gEW, THR>>>(ea, eidx, e1w1, e1b1);

    // layer 2 (k_T consumes agg/xr directly; node-1 epilogue fused)
    k_T<<<148, 512>>>(nullptr, e2w2, e2b2, root2, bias2, nullptr,
                      bn1g, bn1b, bn1m, bn1v);
    k_edge<<<gEW, THR>>>(ea, eidx, e2w1, e2b1);

    // node-2 + pool + fused readout (last block)
    k_node2<<<gN8, THR>>>(bn2g, bn2b, bn2m, bn2v, batch,
                          r1w, r1b, r2w, r2b, out);
}